// round 13
// baseline (speedup 1.0000x reference)
#include <cuda_runtime.h>
#include <cuda_bf16.h>
#include <math.h>
#include <stdint.h>

#define B_ 1024
#define F_ 4096
#define V_ 20000
#define NPAD 20096
#define E_ 512
#define H_ 1024
#define L_ 20
#define D_ 4
#define G4H 4096
#define KCAT 1536
#define KP_GATE (3*KCAT)   // 4608
#define KP_LOG  (3*H_)     // 3072
#define KP_TS   (3*F_)     // 12288
#define NTPAD 160

typedef __nv_bfloat16 bf16;

// ---------------- scratch ----------------
__device__ __align__(256) bf16 d_probs[(size_t)NPAD*KP_LOG];
__device__ __align__(256) bf16 d_wcat_s[(size_t)G4H*KP_GATE];
__device__ __align__(256) bf16 d_wcat_r[(size_t)G4H*KP_GATE];
__device__ __align__(256) bf16 d_affs[(size_t)H_*KP_TS];
__device__ __align__(256) bf16 d_affr[(size_t)F_*KP_LOG];
__device__ __align__(256) bf16 d_a5[(size_t)5*B_*KP_TS];
__device__ __align__(256) bf16 d_rdup[(size_t)B_*KP_TS];
__device__ __align__(256) bf16 d_wact[(size_t)B_*KP_GATE];     // sender activations
__device__ __align__(256) bf16 d_wact2[(size_t)B_*KP_GATE];    // receiver activations
__device__ __align__(256) bf16 d_hdup[(size_t)B_*KP_LOG];      // sender h
__device__ __align__(256) bf16 d_hdup2[(size_t)B_*KP_LOG];     // receiver h

__device__ __align__(256) float g_hf[B_*H_];
__device__ __align__(256) float g_c[B_*H_];
__device__ __align__(256) float g_c2[B_*H_];
__device__ __align__(256) float g_gates[(size_t)B_*G4H];
__device__ __align__(256) float g_gates2[(size_t)B_*G4H];
__device__ __align__(256) float g_logits[(size_t)B_*NPAD];
__device__ __align__(256) float g_rf[(size_t)B_*F_];
__device__ __align__(256) float g_sc[(size_t)5*B_*B_];
__device__ __align__(256) float g_pmax[(size_t)B_*NTPAD];
__device__ __align__(256) int   g_pidx[(size_t)B_*NTPAD];
__device__ int   g_msg[L_*B_];
__device__ float g_logprob[B_];
__device__ float g_bias_s[G4H];
__device__ float g_bias_r[G4H];
__device__ float g_pbias[NPAD];
__device__ float g_lsum[B_];
__device__ float g_tp[B_];
__device__ float g_dp[D_*B_];

// ---------------- helpers ----------------
__device__ __forceinline__ uint32_t smem_u32(const void* p) {
    uint32_t a;
    asm("{ .reg .u64 t; cvta.to.shared.u64 t, %1; cvt.u32.u64 %0, t; }" : "=r"(a) : "l"(p));
    return a;
}
__device__ __forceinline__ void split2(float x, bf16& h, bf16& l) {
    h = __float2bfloat16(x);
    l = __float2bfloat16(x - __bfloat162float(h));
}
__device__ __forceinline__ float sigf(float x) { return 1.0f / (1.0f + expf(-x)); }

// ---------------- bf16 NT GEMM via mma.sync: BM=256, BN=128, 512 threads ----------------
// MODE: 0 = store C (+bias if non-null), 1 = fused per-row argmax partials
// gridDim.z == 2 selects second problem set (A2/B2/bias2/C2) for z==1.
#define A_TILE_B 32768
#define B_TILE_B 16384
#define STAGE_BYTES (A_TILE_B + B_TILE_B)   // 49152
#define SMEM_G (3*STAGE_BYTES)              // 147456

template<int MODE>
__global__ void __launch_bounds__(512, 1)
gemm_bf16(const bf16* __restrict__ A, const bf16* __restrict__ Bw,
          const float* __restrict__ bias, float* __restrict__ C,
          int Kp, int Ncols, int swapRaster,
          float* __restrict__ pmax, int* __restrict__ pidx,
          const bf16* __restrict__ A2, const bf16* __restrict__ B2,
          const float* __restrict__ bias2, float* __restrict__ C2)
{
    extern __shared__ char smem_[];
    const uint32_t sbase = smem_u32(smem_);
    if (blockIdx.z == 1) { A = A2; Bw = B2; bias = bias2; C = C2; }
    int bm, bn;
    if (swapRaster) { bm = blockIdx.y * 256; bn = blockIdx.x * 128; }
    else            { bm = blockIdx.x * 256; bn = blockIdx.y * 128; }
    const int tid = threadIdx.x, lane = tid & 31, wid = tid >> 5;
    const int wm = wid >> 2, wn = wid & 3;     // 4 x 4 warps; warp tile 64 x 32

    const char* Ag = (const char*)(A + (size_t)bm * Kp);
    const char* Bg = (const char*)(Bw + (size_t)bn * Kp);
    const size_t rowB = (size_t)Kp * 2;
    const int nk = Kp >> 6;

    auto loadTile = [&](int ck, int st) {
        uint32_t sp = sbase + st * STAGE_BYTES;
        size_t ko = (size_t)ck * 128;
        // A: 256 rows x 128B
#pragma unroll
        for (int it = 0; it < 4; it++) {
            int r = it * 64 + (tid >> 3);
            int s = tid & 7;
            uint32_t sa = sp + (uint32_t)r * 128 + ((s ^ (r & 7)) * 16);
            const char* ga = Ag + ko + (size_t)r * rowB + s * 16;
            asm volatile("cp.async.cg.shared.global [%0], [%1], 16;" :: "r"(sa), "l"(ga));
        }
        // B: 128 rows x 128B
        uint32_t SB = sp + A_TILE_B;
#pragma unroll
        for (int it = 0; it < 2; it++) {
            int r = it * 64 + (tid >> 3);
            int s = tid & 7;
            uint32_t sa = SB + (uint32_t)r * 128 + ((s ^ (r & 7)) * 16);
            const char* ga = Bg + ko + (size_t)r * rowB + s * 16;
            asm volatile("cp.async.cg.shared.global [%0], [%1], 16;" :: "r"(sa), "l"(ga));
        }
        asm volatile("cp.async.commit_group;" ::: "memory");
    };

    float acc[4][4][4];
#pragma unroll
    for (int a = 0; a < 4; a++)
#pragma unroll
        for (int b = 0; b < 4; b++)
#pragma unroll
            for (int q = 0; q < 4; q++) acc[a][b][q] = 0.0f;

    loadTile(0, 0);
    if (nk > 1) loadTile(1, 1);

    for (int i = 0; i < nk; i++) {
        if (i + 1 < nk) asm volatile("cp.async.wait_group 1;" ::: "memory");
        else            asm volatile("cp.async.wait_group 0;" ::: "memory");
        __syncthreads();
        uint32_t Ab = sbase + (i % 3) * STAGE_BYTES;
        uint32_t Bb = Ab + A_TILE_B;
#pragma unroll
        for (int j = 0; j < 4; j++) {
            uint32_t af[4][4], bfr[2][4];
            int ar = lane & 15;
            int asel = 2 * j + (lane >> 4);
#pragma unroll
            for (int mi = 0; mi < 4; mi++) {
                int row = wm * 64 + mi * 16 + ar;
                uint32_t ad = Ab + row * 128 + ((asel ^ (row & 7)) * 16);
                asm volatile("ldmatrix.sync.aligned.m8n8.x4.shared.b16 {%0,%1,%2,%3}, [%4];"
                    : "=r"(af[mi][0]), "=r"(af[mi][1]), "=r"(af[mi][2]), "=r"(af[mi][3])
                    : "r"(ad));
            }
            int bsel = 2 * j + ((lane >> 3) & 1);
#pragma unroll
            for (int p = 0; p < 2; p++) {
                int nr = wn * 32 + (p * 2 + (lane >> 4)) * 8 + (lane & 7);
                uint32_t bd = Bb + nr * 128 + ((bsel ^ (nr & 7)) * 16);
                asm volatile("ldmatrix.sync.aligned.m8n8.x4.shared.b16 {%0,%1,%2,%3}, [%4];"
                    : "=r"(bfr[p][0]), "=r"(bfr[p][1]), "=r"(bfr[p][2]), "=r"(bfr[p][3])
                    : "r"(bd));
            }
#pragma unroll
            for (int mi = 0; mi < 4; mi++)
#pragma unroll
                for (int ni = 0; ni < 4; ni++) {
                    uint32_t b0 = bfr[ni >> 1][(ni & 1) * 2];
                    uint32_t b1 = bfr[ni >> 1][(ni & 1) * 2 + 1];
                    asm volatile(
                        "mma.sync.aligned.m16n8k16.row.col.f32.bf16.bf16.f32 "
                        "{%0,%1,%2,%3}, {%4,%5,%6,%7}, {%8,%9}, {%0,%1,%2,%3};"
                        : "+f"(acc[mi][ni][0]), "+f"(acc[mi][ni][1]),
                          "+f"(acc[mi][ni][2]), "+f"(acc[mi][ni][3])
                        : "r"(af[mi][0]), "r"(af[mi][1]), "r"(af[mi][2]), "r"(af[mi][3]),
                          "r"(b0), "r"(b1));
                }
        }
        if (i + 2 < nk) loadTile(i + 2, (i + 2) % 3);
    }

    if (MODE == 0) {
#pragma unroll
        for (int mi = 0; mi < 4; mi++) {
            int row = bm + wm * 64 + mi * 16 + (lane >> 2);
#pragma unroll
            for (int ni = 0; ni < 4; ni++) {
                int col = bn + wn * 32 + ni * 8 + (lane & 3) * 2;
                float b0 = bias ? bias[col] : 0.0f;
                float b1 = bias ? bias[col + 1] : 0.0f;
                float2 v;
                v.x = acc[mi][ni][0] + b0; v.y = acc[mi][ni][1] + b1;
                *(float2*)&C[(size_t)row * Ncols + col] = v;
                v.x = acc[mi][ni][2] + b0; v.y = acc[mi][ni][3] + b1;
                *(float2*)&C[(size_t)(row + 8) * Ncols + col] = v;
            }
        }
    } else {
        __syncthreads();
        float* smax = (float*)smem_;                 // 256 rows x 4 warps
        int*   sidx = (int*)(smem_ + 4096);
#pragma unroll
        for (int mi = 0; mi < 4; mi++) {
            float mv0 = -3.4e38f, mv1 = -3.4e38f;
            int ix0 = V_, ix1 = V_;
#pragma unroll
            for (int ni = 0; ni < 4; ni++) {
                int colb = bn + wn * 32 + ni * 8 + (lane & 3) * 2;
                float bb0 = bias[colb], bb1 = bias[colb + 1];
                float v;
                if (colb < V_) {
                    v = acc[mi][ni][0] + bb0; if (v > mv0) { mv0 = v; ix0 = colb; }
                    v = acc[mi][ni][2] + bb0; if (v > mv1) { mv1 = v; ix1 = colb; }
                }
                if (colb + 1 < V_) {
                    v = acc[mi][ni][1] + bb1; if (v > mv0) { mv0 = v; ix0 = colb + 1; }
                    v = acc[mi][ni][3] + bb1; if (v > mv1) { mv1 = v; ix1 = colb + 1; }
                }
            }
#pragma unroll
            for (int o = 1; o < 4; o <<= 1) {
                float vo = __shfl_xor_sync(~0u, mv0, o); int io = __shfl_xor_sync(~0u, ix0, o);
                if (vo > mv0 || (vo == mv0 && io < ix0)) { mv0 = vo; ix0 = io; }
                vo = __shfl_xor_sync(~0u, mv1, o); io = __shfl_xor_sync(~0u, ix1, o);
                if (vo > mv1 || (vo == mv1 && io < ix1)) { mv1 = vo; ix1 = io; }
            }
            if ((lane & 3) == 0) {
                int lr = wm * 64 + mi * 16 + (lane >> 2);
                smax[lr * 4 + wn] = mv0; sidx[lr * 4 + wn] = ix0;
                smax[(lr + 8) * 4 + wn] = mv1; sidx[(lr + 8) * 4 + wn] = ix1;
            }
        }
        __syncthreads();
        if (tid < 256) {
            float v = -3.4e38f; int ix = V_;
#pragma unroll
            for (int w = 0; w < 4; w++) {
                float vv = smax[tid * 4 + w]; int ii = sidx[tid * 4 + w];
                if (vv > v || (vv == v && ii < ix)) { v = vv; ix = ii; }
            }
            int gnt = swapRaster ? blockIdx.x : blockIdx.y;
            pmax[(size_t)(bm + tid) * NTPAD + gnt] = v;
            pidx[(size_t)(bm + tid) * NTPAD + gnt] = ix;
        }
    }
}

// ---------------- LSTM pointwise (gates packed col=4j+gate); dual-capable ----------------
__global__ void lstm_split_packed(const float* __restrict__ gates, float* __restrict__ c,
                                  bf16* __restrict__ hdup, bf16* __restrict__ wact,
                                  const float* __restrict__ gates2, float* __restrict__ c2,
                                  bf16* __restrict__ hdup2, bf16* __restrict__ wact2,
                                  int n) {
    int idx = blockIdx.x * blockDim.x + threadIdx.x;
    if (idx >= n) return;
    const float* G = gates; float* C = c; bf16* Hd = hdup; bf16* Wa = wact;
    if (idx >= B_ * H_) {
        idx -= B_ * H_;
        G = gates2; C = c2; Hd = hdup2; Wa = wact2;
    }
    int b = idx >> 10, j = idx & (H_ - 1);
    float4 g = *(const float4*)(G + (size_t)b * G4H + 4 * j);   // i,f,g,o
    float cn = sigf(g.y) * C[idx] + sigf(g.x) * tanhf(g.z);
    C[idx] = cn;
    float hv = sigf(g.w) * tanhf(cn);
    bf16 h, l; split2(hv, h, l);
    size_t oh = (size_t)b * KP_LOG;
    Hd[oh + j] = h; Hd[oh + H_ + j] = h; Hd[oh + 2 * H_ + j] = l;
    size_t ow = (size_t)b * KP_GATE + E_;
    Wa[ow + j] = h; Wa[ow + KCAT + j] = h; Wa[ow + 2 * KCAT + j] = l;
}

// ---------------- prep kernels ----------------
__global__ void split_dupA2(const float* __restrict__ src, bf16* __restrict__ dst,
                            int K, size_t n) {
    size_t i = ((size_t)blockIdx.x * blockDim.x + threadIdx.x) * 2;
    if (i >= n) return;
    size_t r = i / K; int k = (int)(i % K);
    float2 v = *(const float2*)(src + i);
    bf16 h0, l0, h1, l1; split2(v.x, h0, l0); split2(v.y, h1, l1);
    __nv_bfloat162 H2, L2; H2.x = h0; H2.y = h1; L2.x = l0; L2.y = l1;
    size_t base = r * (size_t)(3 * K) + k;
    *(__nv_bfloat162*)(dst + base) = H2;
    *(__nv_bfloat162*)(dst + base + K) = H2;
    *(__nv_bfloat162*)(dst + base + 2 * K) = L2;
}

__global__ void split_dupB2(const float* __restrict__ src, bf16* __restrict__ dst,
                            int K, size_t n) {
    size_t i = ((size_t)blockIdx.x * blockDim.x + threadIdx.x) * 2;
    if (i >= n) return;
    size_t r = i / K; int k = (int)(i % K);
    float2 v = *(const float2*)(src + i);
    bf16 h0, l0, h1, l1; split2(v.x, h0, l0); split2(v.y, h1, l1);
    __nv_bfloat162 H2, L2; H2.x = h0; H2.y = h1; L2.x = l0; L2.y = l1;
    size_t base = r * (size_t)(3 * K) + k;
    *(__nv_bfloat162*)(dst + base) = H2;
    *(__nv_bfloat162*)(dst + base + K) = L2;
    *(__nv_bfloat162*)(dst + base + 2 * K) = H2;
}

__global__ void split_dupB_pad2(const float* __restrict__ src, bf16* __restrict__ dst,
                                int srcRows, int dstRows, int K) {
    size_t i = ((size_t)blockIdx.x * blockDim.x + threadIdx.x) * 2;
    if (i >= (size_t)dstRows * K) return;
    size_t r = i / K; int k = (int)(i % K);
    float2 v = make_float2(0.f, 0.f);
    if (r < (size_t)srcRows) v = *(const float2*)(src + r * K + k);
    bf16 h0, l0, h1, l1; split2(v.x, h0, l0); split2(v.y, h1, l1);
    __nv_bfloat162 H2, L2; H2.x = h0; H2.y = h1; L2.x = l0; L2.y = l1;
    size_t base = r * (size_t)(3 * K) + k;
    *(__nv_bfloat162*)(dst + base) = H2;
    *(__nv_bfloat162*)(dst + base + K) = L2;
    *(__nv_bfloat162*)(dst + base + 2 * K) = H2;
}

__global__ void split_cat_perm2(const float* __restrict__ W1, const float* __restrict__ W2,
                                bf16* __restrict__ dst, int c1, int c2) {
    int K = c1 + c2;
    size_t i = ((size_t)blockIdx.x * blockDim.x + threadIdx.x) * 2;
    if (i >= (size_t)G4H * K) return;
    size_t r = i / K; int k = (int)(i % K);
    size_t rs = (size_t)((r & 3) * H_ + (r >> 2));
    float2 v = (k < c1) ? *(const float2*)(W1 + rs * c1 + k)
                        : *(const float2*)(W2 + rs * c2 + (k - c1));
    bf16 h0, l0, h1, l1; split2(v.x, h0, l0); split2(v.y, h1, l1);
    __nv_bfloat162 H2, L2; H2.x = h0; H2.y = h1; L2.x = l0; L2.y = l1;
    size_t base = r * (size_t)(3 * K) + k;
    *(__nv_bfloat162*)(dst + base) = H2;
    *(__nv_bfloat162*)(dst + base + K) = L2;
    *(__nv_bfloat162*)(dst + base + 2 * K) = H2;
}

__global__ void add_vec_perm(const float* a, const float* b, float* o) {
    int n = blockIdx.x * blockDim.x + threadIdx.x;
    if (n < G4H) {
        int s = (n & 3) * H_ + (n >> 2);
        o[n] = a[s] + b[s];
    }
}

__global__ void pad_bias(const float* __restrict__ src, float* __restrict__ dst) {
    int i = blockIdx.x * blockDim.x + threadIdx.x;
    if (i < NPAD) dst[i] = (i < V_) ? src[i] : -1e30f;
}

__global__ void zero_f(float* p, size_t n) {
    size_t i = (size_t)blockIdx.x * blockDim.x + threadIdx.x;
    if (i < n) p[i] = 0.0f;
}

__global__ void zero_w(uint32_t* p, size_t n) {
    size_t i = (size_t)blockIdx.x * blockDim.x + threadIdx.x;
    if (i < n) p[i] = 0u;
}

__global__ void gather_split(const float* __restrict__ emb, const int* __restrict__ tok,
                             int isStart, bf16* __restrict__ wact) {
    int b = blockIdx.x;
    int t = isStart ? tok[0] : tok[b];
    size_t o = (size_t)b * KP_GATE;
    for (int c = threadIdx.x; c < E_; c += 128) {
        bf16 h, l; split2(emb[(size_t)t * E_ + c], h, l);
        wact[o + c] = h; wact[o + KCAT + c] = h; wact[o + 2 * KCAT + c] = l;
    }
}

// fused: combine argmax partials -> msg[b], then gather emb_s -> wact AND emb_r -> wact2
__global__ void argmax_gather(const float* __restrict__ pmax, const int* __restrict__ pidx,
                              int nt, int* __restrict__ msg,
                              const float* __restrict__ embS, bf16* __restrict__ wact,
                              const float* __restrict__ embR, bf16* __restrict__ wact2) {
    int b = blockIdx.x, tid = threadIdx.x, lane = tid & 31;
    __shared__ int stok;
    if (tid < 32) {
        float v = -3.4e38f; int ix = 0x7fffffff;
        for (int t = lane; t < nt; t += 32) {
            float vv = pmax[(size_t)b * NTPAD + t];
            int ii = pidx[(size_t)b * NTPAD + t];
            if (vv > v || (vv == v && ii < ix)) { v = vv; ix = ii; }
        }
#pragma unroll
        for (int o = 16; o > 0; o >>= 1) {
            float vo = __shfl_xor_sync(~0u, v, o); int io = __shfl_xor_sync(~0u, ix, o);
            if (vo > v || (vo == v && io < ix)) { v = vo; ix = io; }
        }
        if (!lane) { msg[b] = ix; stok = ix; }
    }
    __syncthreads();
    int t = stok;
    size_t o = (size_t)b * KP_GATE;
    for (int c = tid; c < E_; c += 128) {
        bf16 h, l;
        split2(embS[(size_t)t * E_ + c], h, l);
        wact[o + c] = h; wact[o + KCAT + c] = h; wact[o + 2 * KCAT + c] = l;
        split2(embR[(size_t)t * E_ + c], h, l);
        wact2[o + c] = h; wact2[o + KCAT + c] = h; wact2[o + 2 * KCAT + c] = l;
    }
}

__global__ void argmax_row(const float* __restrict__ logits, int* __restrict__ msg,
                           float* __restrict__ logprob) {
    int b = blockIdx.x;
    const float* row = logits + (size_t)b * NPAD;
    int tid = threadIdx.x;
    float best = -3.4e38f; int bi = 0x7fffffff;
    for (int v = tid; v < V_; v += 256) {
        float x = row[v];
        if (x > best) { best = x; bi = v; }
    }
    __shared__ float sv[256];
    __shared__ int   si[256];
    sv[tid] = best; si[tid] = bi;
    __syncthreads();
    for (int s = 128; s > 0; s >>= 1) {
        if (tid < s) {
            if (sv[tid + s] > sv[tid] ||
                (sv[tid + s] == sv[tid] && si[tid + s] < si[tid])) {
                sv[tid] = sv[tid + s]; si[tid] = si[tid + s];
            }
        }
        __syncthreads();
    }
    float m = sv[0];
    if (tid == 0) msg[b] = si[0];
    __syncthreads();
    float s = 0.0f;
    for (int v = tid; v < V_; v += 256) s += expf(row[v] - m);
    sv[tid] = s;
    __syncthreads();
    for (int st = 128; st > 0; st >>= 1) {
        if (tid < st) sv[tid] += sv[tid + st];
        __syncthreads();
    }
    if (tid == 0) logprob[b] = -logf(sv[0]);
}

__global__ void hsplit_wact(const float* __restrict__ src,
                            bf16* __restrict__ hdup, bf16* __restrict__ wact) {
    int idx = blockIdx.x * blockDim.x + threadIdx.x;
    if (idx >= B_ * H_) return;
    int b = idx >> 10, j = idx & (H_ - 1);
    bf16 h, l; split2(src[idx], h, l);
    size_t oh = (size_t)b * KP_LOG;
    hdup[oh + j] = h; hdup[oh + H_ + j] = h; hdup[oh + 2 * H_ + j] = l;
    size_t ow = (size_t)b * KP_GATE + E_;
    wact[ow + j] = h; wact[ow + KCAT + j] = h; wact[ow + 2 * KCAT + j] = l;
}

__global__ void rsplit(const float* __restrict__ src, bf16* __restrict__ dst) {
    int idx = blockIdx.x * blockDim.x + threadIdx.x;
    if (idx >= B_ * F_) return;
    int b = idx >> 12, k = idx & (F_ - 1);
    bf16 h, l; split2(src[idx], h, l);
    size_t base = (size_t)b * KP_TS;
    dst[base + k] = h; dst[base + F_ + k] = l; dst[base + 2 * F_ + k] = h;
}

__global__ void reduce_rows(const float* __restrict__ sc, const float* __restrict__ lp,
                            float* __restrict__ lsum, float* __restrict__ tp,
                            float* __restrict__ dp) {
    int b = blockIdx.x, tid = threadIdx.x;
    float l = 0.f, t = 0.f, d0 = 0.f, d1 = 0.f, d2 = 0.f, d3 = 0.f;
    const float* tsr = sc + (size_t)b * B_;
    const float* dr0 = sc + (size_t)(1024 + b) * B_;
    const float* dr1 = sc + (size_t)(2048 + b) * B_;
    const float* dr2 = sc + (size_t)(3072 + b) * B_;
    const float* dr3 = sc + (size_t)(4096 + b) * B_;
    for (int k = tid; k < B_; k += 256) {
        float tv = tsr[k];
        float v0 = dr0[k], v1 = dr1[k], v2 = dr2[k], v3 = dr3[k];
        float h = fmaxf(0.f, 1.f - tv + v0) + fmaxf(0.f, 1.f - tv + v1)
                + fmaxf(0.f, 1.f - tv + v2) + fmaxf(0.f, 1.f - tv + v3);
        l += h * lp[k];
        t += expf(tv);
        d0 += expf(v0); d1 += expf(v1); d2 += expf(v2); d3 += expf(v3);
    }
    __shared__ float sh[6][256];
    sh[0][tid] = l; sh[1][tid] = t; sh[2][tid] = d0;
    sh[3][tid] = d1; sh[4][tid] = d2; sh[5][tid] = d3;
    __syncthreads();
    for (int s = 128; s > 0; s >>= 1) {
        if (tid < s)
            for (int q = 0; q < 6; q++) sh[q][tid] += sh[q][tid + s];
        __syncthreads();
    }
    if (tid == 0) {
        lsum[b] = sh[0][0]; tp[b] = sh[1][0];
        dp[b] = sh[2][0]; dp[B_ + b] = sh[3][0];
        dp[2 * B_ + b] = sh[4][0]; dp[3 * B_ + b] = sh[5][0];
    }
}

__global__ void finalize(const float* __restrict__ lsum, const float* __restrict__ tp,
                         const float* __restrict__ dp, float* __restrict__ out) {
    int tid = threadIdx.x;
    float lo = 0.f, an = 0.f;
    for (int b = tid; b < B_; b += 256) {
        lo += lsum[b];
        float t = tp[b];
        bool ok = (t >= dp[b]) && (t >= dp[B_ + b]) &&
                  (t >= dp[2 * B_ + b]) && (t >= dp[3 * B_ + b]);
        an += ok ? 1.0f : 0.0f;
    }
    __shared__ float s0[256], s1[256];
    s0[tid] = lo; s1[tid] = an;
    __syncthreads();
    for (int s = 128; s > 0; s >>= 1) {
        if (tid < s) { s0[tid] += s0[tid + s]; s1[tid] += s1[tid + s]; }
        __syncthreads();
    }
    if (tid == 0) {
        out[0] = -s0[0] / ((float)B_ * (float)B_);
        out[1] = s1[0] / (float)B_;
    }
}

// ---------------- host ----------------
#define SYM(p, g) cudaGetSymbolAddress((void**)&p, g)
static inline size_t gb1(size_t n) { return (n + 255) / 256; }
static inline size_t gb2(size_t n) { return (n / 2 + 255) / 256; }

extern "C" void kernel_launch(void* const* d_in, const int* in_sizes, int n_in,
                              void* d_out, int out_size) {
    (void)in_sizes; (void)n_in; (void)out_size;
    const float* target      = (const float*)d_in[0];
    const float* distractors = (const float*)d_in[1];
    const int*   start_tok   = (const int*)d_in[2];
    const float* emb_s   = (const float*)d_in[4];
    const float* Wih_s   = (const float*)d_in[5];
    const float* Whh_s   = (const float*)d_in[6];
    const float* bih_s   = (const float*)d_in[7];
    const float* bhh_s   = (const float*)d_in[8];
    const float* aff_s_W = (const float*)d_in[9];
    const float* aff_s_b = (const float*)d_in[10];
    const float* probs_W = (const float*)d_in[11];
    const float* probs_b = (const float*)d_in[12];
    const float* emb_r   = (const float*)d_in[13];
    const float* Wih_r   = (const float*)d_in[14];
    const float* Whh_r   = (const float*)d_in[15];
    const float* bih_r   = (const float*)d_in[16];
    const float* bhh_r   = (const float*)d_in[17];
    const float* aff_r_W = (const float*)d_in[18];
    const float* aff_r_b = (const float*)d_in[19];
    float* out = (float*)d_out;

    bf16 *pProbs, *pWcS, *pWcR, *pAfS, *pAfR, *pA5, *pRd, *pWa, *pWa2, *pHd, *pHd2;
    float *pHf, *pC, *pC2, *pG, *pG2, *pLg, *pRf, *pSc, *pLp;
    float *pBs, *pBr, *pPb, *pLs, *pTp, *pDp, *pPm;
    int *pMsg, *pPi;
    SYM(pProbs, d_probs); SYM(pWcS, d_wcat_s); SYM(pWcR, d_wcat_r);
    SYM(pAfS, d_affs); SYM(pAfR, d_affr); SYM(pA5, d_a5); SYM(pRd, d_rdup);
    SYM(pWa, d_wact); SYM(pWa2, d_wact2); SYM(pHd, d_hdup); SYM(pHd2, d_hdup2);
    SYM(pHf, g_hf); SYM(pC, g_c); SYM(pC2, g_c2); SYM(pG, g_gates); SYM(pG2, g_gates2);
    SYM(pLg, g_logits); SYM(pRf, g_rf); SYM(pSc, g_sc); SYM(pLp, g_logprob);
    SYM(pBs, g_bias_s); SYM(pBr, g_bias_r); SYM(pPb, g_pbias);
    SYM(pLs, g_lsum); SYM(pTp, g_tp); SYM(pDp, g_dp); SYM(pMsg, g_msg);
    SYM(pPm, g_pmax); SYM(pPi, g_pidx);

    cudaFuncSetAttribute(gemm_bf16<0>, cudaFuncAttributeMaxDynamicSharedMemorySize, SMEM_G);
    cudaFuncSetAttribute(gemm_bf16<1>, cudaFuncAttributeMaxDynamicSharedMemorySize, SMEM_G);

    // ---- prep ----
    add_vec_perm<<<(G4H + 255) / 256, 256>>>(bih_s, bhh_s, pBs);
    add_vec_perm<<<(G4H + 255) / 256, 256>>>(bih_r, bhh_r, pBr);
    pad_bias<<<(NPAD + 255) / 256, 256>>>(probs_b, pPb);
    split_dupA2<<<gb2((size_t)B_ * F_), 256>>>(target, pA5, F_, (size_t)B_ * F_);
    split_dupA2<<<gb2((size_t)D_ * B_ * F_), 256>>>(distractors, pA5 + (size_t)B_ * KP_TS,
                                                    F_, (size_t)D_ * B_ * F_);
    split_dupB2<<<gb2((size_t)H_ * F_), 256>>>(aff_s_W, pAfS, F_, (size_t)H_ * F_);
    split_dupB2<<<gb2((size_t)F_ * H_), 256>>>(aff_r_W, pAfR, H_, (size_t)F_ * H_);
    split_dupB_pad2<<<gb2((size_t)NPAD * H_), 256>>>(probs_W, pProbs, V_, NPAD, H_);
    split_cat_perm2<<<gb2((size_t)G4H * KCAT), 256>>>(Wih_s, Whh_s, pWcS, E_, H_);
    split_cat_perm2<<<gb2((size_t)G4H * KCAT), 256>>>(Wih_r, Whh_r, pWcR, E_, H_);

    // ---- init ----
    zero_f<<<gb1((size_t)B_ * H_), 256>>>(pC, (size_t)B_ * H_);
    zero_f<<<gb1((size_t)B_ * H_), 256>>>(pC2, (size_t)B_ * H_);
    zero_w<<<gb1((size_t)B_ * KP_GATE / 2), 256>>>((uint32_t*)pWa2, (size_t)B_ * KP_GATE / 2);
    gemm_bf16<0><<<dim3(4, 8, 1), 512, SMEM_G>>>(pA5, pAfS, aff_s_b, pHf, KP_TS, H_, 0,
                                                 nullptr, nullptr,
                                                 nullptr, nullptr, nullptr, nullptr);
    hsplit_wact<<<gb1((size_t)B_ * H_), 256>>>(pHf, pHd, pWa);
    gather_split<<<B_, 128>>>(emb_s, start_tok, 1, pWa);

    // ---- main loop: sender step s; receiver step s-1 rides along (z=2) ----
    for (int s = 0; s < L_; s++) {
        int dual = (s >= 1);
        if (dual) {
            gemm_bf16<0><<<dim3(4, 32, 2), 512, SMEM_G>>>(pWa, pWcS, pBs, pG, KP_GATE, G4H, 0,
                                                          nullptr, nullptr,
                                                          pWa2, pWcR, pBr, pG2);
            lstm_split_packed<<<gb1(2 * (size_t)B_ * H_), 256>>>(pG, pC, pHd, pWa,
                                                                 pG2, pC2, pHd2, pWa2,
                                                                 2 * B_ * H_);
        } else {
            gemm_bf16<0><<<dim3(4, 32, 1), 512, SMEM_G>>>(pWa, pWcS, pBs, pG, KP_GATE, G4H, 0,
                                                          nullptr, nullptr,
                                                          nullptr, nullptr, nullptr, nullptr);
            lstm_split_packed<<<gb1((size_t)B_ * H_), 256>>>(pG, pC, pHd, pWa,
                                                             nullptr, nullptr, nullptr, nullptr,
                                                             B_ * H_);
        }
        if (s < L_ - 1) {
            gemm_bf16<1><<<dim3(4, 157, 1), 512, SMEM_G>>>(pHd, pProbs, pPb, nullptr, KP_LOG,
                                                           NPAD, 0, pPm, pPi,
                                                           nullptr, nullptr, nullptr, nullptr);
            argmax_gather<<<B_, 128>>>(pPm, pPi, 157, pMsg + s * B_, emb_s, pWa, emb_r, pWa2);
        } else {
            gemm_bf16<0><<<dim3(4, 157, 1), 512, SMEM_G>>>(pHd, pProbs, pPb, pLg, KP_LOG, NPAD,
                                                           0, nullptr, nullptr,
                                                           nullptr, nullptr, nullptr, nullptr);
            argmax_row<<<B_, 256>>>(pLg, pMsg + s * B_, pLp);
        }
    }

    // ---- receiver final step (r = L-1) ----
    gather_split<<<B_, 128>>>(emb_r, pMsg + (L_ - 1) * B_, 0, pWa2);
    gemm_bf16<0><<<dim3(4, 32, 1), 512, SMEM_G>>>(pWa2, pWcR, pBr, pG2, KP_GATE, G4H, 0,
                                                  nullptr, nullptr,
                                                  nullptr, nullptr, nullptr, nullptr);
    lstm_split_packed<<<gb1((size_t)B_ * H_), 256>>>(pG2, pC2, pHd2, pWa2,
                                                     nullptr, nullptr, nullptr, nullptr,
                                                     B_ * H_);

    // ---- r, ts/ds, loss ----
    gemm_bf16<0><<<dim3(4, 32, 1), 512, SMEM_G>>>(pHd2, pAfR, aff_r_b, pRf, KP_LOG, F_, 0,
                                                  nullptr, nullptr,
                                                  nullptr, nullptr, nullptr, nullptr);
    rsplit<<<gb1((size_t)B_ * F_), 256>>>(pRf, pRd);
    gemm_bf16<0><<<dim3(8, 20, 1), 512, SMEM_G>>>(pA5, pRd, nullptr, pSc, KP_TS, B_, 1,
                                                  nullptr, nullptr,
                                                  nullptr, nullptr, nullptr, nullptr);
    reduce_rows<<<B_, 256>>>(pSc, pLp, pLs, pTp, pDp);
    finalize<<<1, 256>>>(pLs, pTp, pDp, out);
}

// round 16
// speedup vs baseline: 1.1696x; 1.1696x over previous
#include <cuda_runtime.h>
#include <cuda_bf16.h>
#include <math.h>
#include <stdint.h>

#define B_ 1024
#define F_ 4096
#define V_ 20000
#define NPAD 20096
#define E_ 512
#define H_ 1024
#define L_ 20
#define D_ 4
#define G4H 4096
#define KCAT 1536
#define KP_GATE (3*KCAT)   // 4608
#define KP_LOG  (3*H_)     // 3072
#define KP_TS   (3*F_)     // 12288
#define NTPAD 160

typedef __nv_bfloat16 bf16;

// ---------------- scratch ----------------
__device__ __align__(256) bf16 d_probs[(size_t)NPAD*KP_LOG];
__device__ __align__(256) bf16 d_wcat_s[(size_t)G4H*KP_GATE];
__device__ __align__(256) bf16 d_wcat_r[(size_t)G4H*KP_GATE];
__device__ __align__(256) bf16 d_affs[(size_t)H_*KP_TS];
__device__ __align__(256) bf16 d_affr[(size_t)F_*KP_LOG];
__device__ __align__(256) bf16 d_a5[(size_t)5*B_*KP_TS];
__device__ __align__(256) bf16 d_rdup[(size_t)B_*KP_TS];
__device__ __align__(256) bf16 d_wact[(size_t)B_*KP_GATE];     // sender activations
__device__ __align__(256) bf16 d_wact2[(size_t)B_*KP_GATE];    // receiver activations
__device__ __align__(256) bf16 d_hdup[(size_t)B_*KP_LOG];      // sender h
__device__ __align__(256) bf16 d_hdup2[(size_t)B_*KP_LOG];     // receiver h

__device__ __align__(256) float g_hf[B_*H_];
__device__ __align__(256) float g_c[B_*H_];
__device__ __align__(256) float g_c2[B_*H_];
__device__ __align__(256) float g_gates[(size_t)B_*G4H];
__device__ __align__(256) float g_gates2[(size_t)B_*G4H];
__device__ __align__(256) float g_rf[(size_t)B_*F_];
__device__ __align__(256) float g_sc[(size_t)5*B_*B_];
__device__ __align__(256) float g_pmax[(size_t)B_*NTPAD];
__device__ __align__(256) float g_psum[(size_t)B_*NTPAD];
__device__ __align__(256) int   g_pidx[(size_t)B_*NTPAD];
__device__ int   g_msg[L_*B_];
__device__ float g_logprob[B_];
__device__ float g_bias_s[G4H];
__device__ float g_bias_r[G4H];
__device__ float g_pbias[NPAD];
__device__ float g_lsum[B_];
__device__ float g_tp[B_];
__device__ float g_dp[D_*B_];

// ---------------- helpers ----------------
__device__ __forceinline__ uint32_t smem_u32(const void* p) {
    uint32_t a;
    asm("{ .reg .u64 t; cvta.to.shared.u64 t, %1; cvt.u32.u64 %0, t; }" : "=r"(a) : "l"(p));
    return a;
}
__device__ __forceinline__ void split2(float x, bf16& h, bf16& l) {
    h = __float2bfloat16(x);
    l = __float2bfloat16(x - __bfloat162float(h));
}
__device__ __forceinline__ float sigf(float x) { return 1.0f / (1.0f + expf(-x)); }

// ---------------- bf16 NT GEMM via mma.sync (BM=128, BN=128, 256 thr, 2 CTA/SM) ----------------
// MODE: 0 = store C (+bias), 1 = argmax partials, 2 = argmax + logsumexp partials
#define STAGE_BYTES 32768
#define SMEM_G (3*STAGE_BYTES)

template<int MODE>
__global__ void __launch_bounds__(256, 2)
gemm_bf16(const bf16* __restrict__ A, const bf16* __restrict__ Bw,
          const float* __restrict__ bias, float* __restrict__ C,
          int Kp, int Ncols, int swapRaster,
          float* __restrict__ pmax, int* __restrict__ pidx, float* __restrict__ psum,
          const bf16* __restrict__ A2, const bf16* __restrict__ B2,
          const float* __restrict__ bias2, float* __restrict__ C2)
{
    extern __shared__ char smem_[];
    const uint32_t sbase = smem_u32(smem_);
    if (blockIdx.z == 1) { A = A2; Bw = B2; bias = bias2; C = C2; }
    int bm, bn;
    if (swapRaster) { bm = blockIdx.y * 128; bn = blockIdx.x * 128; }
    else            { bm = blockIdx.x * 128; bn = blockIdx.y * 128; }
    const int tid = threadIdx.x, lane = tid & 31, wid = tid >> 5;
    const int wm = wid >> 2, wn = wid & 3;

    const char* Ag = (const char*)(A + (size_t)bm * Kp);
    const char* Bg = (const char*)(Bw + (size_t)bn * Kp);
    const size_t rowB = (size_t)Kp * 2;
    const int nk = Kp >> 6;

    auto loadTile = [&](int ck, int st) {
        uint32_t sp = sbase + st * STAGE_BYTES;
        size_t ko = (size_t)ck * 128;
#pragma unroll
        for (int h = 0; h < 2; h++) {
            const char* G = (h ? Bg : Ag) + ko;
            uint32_t S = sp + h * 16384;
#pragma unroll
            for (int it = 0; it < 4; it++) {
                int r = it * 32 + (tid >> 3);
                int s = tid & 7;
                uint32_t sa = S + (uint32_t)r * 128 + ((s ^ (r & 7)) * 16);
                const char* ga = G + (size_t)r * rowB + s * 16;
                asm volatile("cp.async.cg.shared.global [%0], [%1], 16;" :: "r"(sa), "l"(ga));
            }
        }
        asm volatile("cp.async.commit_group;" ::: "memory");
    };

    float acc[4][4][4];
#pragma unroll
    for (int a = 0; a < 4; a++)
#pragma unroll
        for (int b = 0; b < 4; b++)
#pragma unroll
            for (int q = 0; q < 4; q++) acc[a][b][q] = 0.0f;

    loadTile(0, 0);
    if (nk > 1) loadTile(1, 1);

    for (int i = 0; i < nk; i++) {
        if (i + 1 < nk) asm volatile("cp.async.wait_group 1;" ::: "memory");
        else            asm volatile("cp.async.wait_group 0;" ::: "memory");
        __syncthreads();
        uint32_t Ab = sbase + (i % 3) * STAGE_BYTES;
        uint32_t Bb = Ab + 16384;
#pragma unroll
        for (int j = 0; j < 4; j++) {
            uint32_t af[4][4], bfr[2][4];
            int ar = lane & 15;
            int asel = 2 * j + (lane >> 4);
#pragma unroll
            for (int mi = 0; mi < 4; mi++) {
                int row = wm * 64 + mi * 16 + ar;
                uint32_t ad = Ab + row * 128 + ((asel ^ (row & 7)) * 16);
                asm volatile("ldmatrix.sync.aligned.m8n8.x4.shared.b16 {%0,%1,%2,%3}, [%4];"
                    : "=r"(af[mi][0]), "=r"(af[mi][1]), "=r"(af[mi][2]), "=r"(af[mi][3])
                    : "r"(ad));
            }
            int bsel = 2 * j + ((lane >> 3) & 1);
#pragma unroll
            for (int p = 0; p < 2; p++) {
                int nr = wn * 32 + (p * 2 + (lane >> 4)) * 8 + (lane & 7);
                uint32_t bd = Bb + nr * 128 + ((bsel ^ (nr & 7)) * 16);
                asm volatile("ldmatrix.sync.aligned.m8n8.x4.shared.b16 {%0,%1,%2,%3}, [%4];"
                    : "=r"(bfr[p][0]), "=r"(bfr[p][1]), "=r"(bfr[p][2]), "=r"(bfr[p][3])
                    : "r"(bd));
            }
#pragma unroll
            for (int mi = 0; mi < 4; mi++)
#pragma unroll
                for (int ni = 0; ni < 4; ni++) {
                    uint32_t b0 = bfr[ni >> 1][(ni & 1) * 2];
                    uint32_t b1 = bfr[ni >> 1][(ni & 1) * 2 + 1];
                    asm volatile(
                        "mma.sync.aligned.m16n8k16.row.col.f32.bf16.bf16.f32 "
                        "{%0,%1,%2,%3}, {%4,%5,%6,%7}, {%8,%9}, {%0,%1,%2,%3};"
                        : "+f"(acc[mi][ni][0]), "+f"(acc[mi][ni][1]),
                          "+f"(acc[mi][ni][2]), "+f"(acc[mi][ni][3])
                        : "r"(af[mi][0]), "r"(af[mi][1]), "r"(af[mi][2]), "r"(af[mi][3]),
                          "r"(b0), "r"(b1));
                }
        }
        if (i + 2 < nk) loadTile(i + 2, (i + 2) % 3);
    }

    if (MODE == 0) {
#pragma unroll
        for (int mi = 0; mi < 4; mi++) {
            int row = bm + wm * 64 + mi * 16 + (lane >> 2);
#pragma unroll
            for (int ni = 0; ni < 4; ni++) {
                int col = bn + wn * 32 + ni * 8 + (lane & 3) * 2;
                float b0 = bias ? bias[col] : 0.0f;
                float b1 = bias ? bias[col + 1] : 0.0f;
                float2 v;
                v.x = acc[mi][ni][0] + b0; v.y = acc[mi][ni][1] + b1;
                *(float2*)&C[(size_t)row * Ncols + col] = v;
                v.x = acc[mi][ni][2] + b0; v.y = acc[mi][ni][3] + b1;
                *(float2*)&C[(size_t)(row + 8) * Ncols + col] = v;
            }
        }
    } else {
        __syncthreads();
        float* smax = (float*)smem_;
        int*   sidx = (int*)(smem_ + 2048);
        float* ssum = (float*)(smem_ + 4096);
#pragma unroll
        for (int mi = 0; mi < 4; mi++) {
            float mv0 = -3.4e38f, mv1 = -3.4e38f;
            int ix0 = V_, ix1 = V_;
#pragma unroll
            for (int ni = 0; ni < 4; ni++) {
                int colb = bn + wn * 32 + ni * 8 + (lane & 3) * 2;
                float bb0 = bias[colb], bb1 = bias[colb + 1];
                float v;
                if (colb < V_) {
                    v = acc[mi][ni][0] + bb0; if (v > mv0) { mv0 = v; ix0 = colb; }
                    v = acc[mi][ni][2] + bb0; if (v > mv1) { mv1 = v; ix1 = colb; }
                }
                if (colb + 1 < V_) {
                    v = acc[mi][ni][1] + bb1; if (v > mv0) { mv0 = v; ix0 = colb + 1; }
                    v = acc[mi][ni][3] + bb1; if (v > mv1) { mv1 = v; ix1 = colb + 1; }
                }
            }
#pragma unroll
            for (int o = 1; o < 4; o <<= 1) {
                float vo = __shfl_xor_sync(~0u, mv0, o); int io = __shfl_xor_sync(~0u, ix0, o);
                if (vo > mv0 || (vo == mv0 && io < ix0)) { mv0 = vo; ix0 = io; }
                vo = __shfl_xor_sync(~0u, mv1, o); io = __shfl_xor_sync(~0u, ix1, o);
                if (vo > mv1 || (vo == mv1 && io < ix1)) { mv1 = vo; ix1 = io; }
            }
            float s0 = 0.f, s1 = 0.f;
            if (MODE == 2) {
                // guard padded cols: mv may be -3.4e38 in an all-padded quad;
                // unguarded exp(acc - mv) would overflow to inf.
#pragma unroll
                for (int ni = 0; ni < 4; ni++) {
                    int colb = bn + wn * 32 + ni * 8 + (lane & 3) * 2;
                    float bb0 = bias[colb], bb1 = bias[colb + 1];
                    if (colb < V_) {
                        s0 += expf(acc[mi][ni][0] + bb0 - mv0);
                        s1 += expf(acc[mi][ni][2] + bb0 - mv1);
                    }
                    if (colb + 1 < V_) {
                        s0 += expf(acc[mi][ni][1] + bb1 - mv0);
                        s1 += expf(acc[mi][ni][3] + bb1 - mv1);
                    }
                }
#pragma unroll
                for (int o = 1; o < 4; o <<= 1) {
                    s0 += __shfl_xor_sync(~0u, s0, o);
                    s1 += __shfl_xor_sync(~0u, s1, o);
                }
            }
            if ((lane & 3) == 0) {
                int lr = wm * 64 + mi * 16 + (lane >> 2);
                smax[lr * 4 + wn] = mv0; sidx[lr * 4 + wn] = ix0;
                smax[(lr + 8) * 4 + wn] = mv1; sidx[(lr + 8) * 4 + wn] = ix1;
                if (MODE == 2) { ssum[lr * 4 + wn] = s0; ssum[(lr + 8) * 4 + wn] = s1; }
            }
        }
        __syncthreads();
        if (tid < 128) {
            float v = -3.4e38f; int ix = V_;
#pragma unroll
            for (int w = 0; w < 4; w++) {
                float vv = smax[tid * 4 + w]; int ii = sidx[tid * 4 + w];
                if (vv > v || (vv == v && ii < ix)) { v = vv; ix = ii; }
            }
            int gnt = swapRaster ? blockIdx.x : blockIdx.y;
            pmax[(size_t)(bm + tid) * NTPAD + gnt] = v;
            pidx[(size_t)(bm + tid) * NTPAD + gnt] = ix;
            if (MODE == 2) {
                float S = 0.f;
#pragma unroll
                for (int w = 0; w < 4; w++) {
                    float sw = ssum[tid * 4 + w];
                    if (sw > 0.f) S += sw * expf(smax[tid * 4 + w] - v);
                }
                psum[(size_t)(bm + tid) * NTPAD + gnt] = S;
            }
        }
    }
}

// ---------------- LSTM pointwise (gates packed col=4j+gate); dual-capable ----------------
__global__ void lstm_split_packed(const float* __restrict__ gates, float* __restrict__ c,
                                  bf16* __restrict__ hdup, bf16* __restrict__ wact,
                                  const float* __restrict__ gates2, float* __restrict__ c2,
                                  bf16* __restrict__ hdup2, bf16* __restrict__ wact2,
                                  int n) {
    int idx = blockIdx.x * blockDim.x + threadIdx.x;
    if (idx >= n) return;
    const float* G = gates; float* C = c; bf16* Hd = hdup; bf16* Wa = wact;
    if (idx >= B_ * H_) {
        idx -= B_ * H_;
        G = gates2; C = c2; Hd = hdup2; Wa = wact2;
    }
    int b = idx >> 10, j = idx & (H_ - 1);
    float4 g = *(const float4*)(G + (size_t)b * G4H + 4 * j);   // i,f,g,o
    float cn = sigf(g.y) * C[idx] + sigf(g.x) * tanhf(g.z);
    C[idx] = cn;
    float hv = sigf(g.w) * tanhf(cn);
    bf16 h, l; split2(hv, h, l);
    size_t oh = (size_t)b * KP_LOG;
    Hd[oh + j] = h; Hd[oh + H_ + j] = h; Hd[oh + 2 * H_ + j] = l;
    size_t ow = (size_t)b * KP_GATE + E_;
    Wa[ow + j] = h; Wa[ow + KCAT + j] = h; Wa[ow + 2 * KCAT + j] = l;
}

// ---------------- prep kernels ----------------
__global__ void split_dupA2(const float* __restrict__ src, bf16* __restrict__ dst,
                            int K, size_t n) {
    size_t i = ((size_t)blockIdx.x * blockDim.x + threadIdx.x) * 2;
    if (i >= n) return;
    size_t r = i / K; int k = (int)(i % K);
    float2 v = *(const float2*)(src + i);
    bf16 h0, l0, h1, l1; split2(v.x, h0, l0); split2(v.y, h1, l1);
    __nv_bfloat162 H2, L2; H2.x = h0; H2.y = h1; L2.x = l0; L2.y = l1;
    size_t base = r * (size_t)(3 * K) + k;
    *(__nv_bfloat162*)(dst + base) = H2;
    *(__nv_bfloat162*)(dst + base + K) = H2;
    *(__nv_bfloat162*)(dst + base + 2 * K) = L2;
}

__global__ void split_dupB2(const float* __restrict__ src, bf16* __restrict__ dst,
                            int K, size_t n) {
    size_t i = ((size_t)blockIdx.x * blockDim.x + threadIdx.x) * 2;
    if (i >= n) return;
    size_t r = i / K; int k = (int)(i % K);
    float2 v = *(const float2*)(src + i);
    bf16 h0, l0, h1, l1; split2(v.x, h0, l0); split2(v.y, h1, l1);
    __nv_bfloat162 H2, L2; H2.x = h0; H2.y = h1; L2.x = l0; L2.y = l1;
    size_t base = r * (size_t)(3 * K) + k;
    *(__nv_bfloat162*)(dst + base) = H2;
    *(__nv_bfloat162*)(dst + base + K) = L2;
    *(__nv_bfloat162*)(dst + base + 2 * K) = H2;
}

__global__ void split_dupB_pad2(const float* __restrict__ src, bf16* __restrict__ dst,
                                int srcRows, int dstRows, int K) {
    size_t i = ((size_t)blockIdx.x * blockDim.x + threadIdx.x) * 2;
    if (i >= (size_t)dstRows * K) return;
    size_t r = i / K; int k = (int)(i % K);
    float2 v = make_float2(0.f, 0.f);
    if (r < (size_t)srcRows) v = *(const float2*)(src + r * K + k);
    bf16 h0, l0, h1, l1; split2(v.x, h0, l0); split2(v.y, h1, l1);
    __nv_bfloat162 H2, L2; H2.x = h0; H2.y = h1; L2.x = l0; L2.y = l1;
    size_t base = r * (size_t)(3 * K) + k;
    *(__nv_bfloat162*)(dst + base) = H2;
    *(__nv_bfloat162*)(dst + base + K) = L2;
    *(__nv_bfloat162*)(dst + base + 2 * K) = H2;
}

__global__ void split_cat_perm2(const float* __restrict__ W1, const float* __restrict__ W2,
                                bf16* __restrict__ dst, int c1, int c2) {
    int K = c1 + c2;
    size_t i = ((size_t)blockIdx.x * blockDim.x + threadIdx.x) * 2;
    if (i >= (size_t)G4H * K) return;
    size_t r = i / K; int k = (int)(i % K);
    size_t rs = (size_t)((r & 3) * H_ + (r >> 2));
    float2 v = (k < c1) ? *(const float2*)(W1 + rs * c1 + k)
                        : *(const float2*)(W2 + rs * c2 + (k - c1));
    bf16 h0, l0, h1, l1; split2(v.x, h0, l0); split2(v.y, h1, l1);
    __nv_bfloat162 H2, L2; H2.x = h0; H2.y = h1; L2.x = l0; L2.y = l1;
    size_t base = r * (size_t)(3 * K) + k;
    *(__nv_bfloat162*)(dst + base) = H2;
    *(__nv_bfloat162*)(dst + base + K) = L2;
    *(__nv_bfloat162*)(dst + base + 2 * K) = H2;
}

__global__ void add_vec_perm(const float* a, const float* b, float* o) {
    int n = blockIdx.x * blockDim.x + threadIdx.x;
    if (n < G4H) {
        int s = (n & 3) * H_ + (n >> 2);
        o[n] = a[s] + b[s];
    }
}

__global__ void pad_bias(const float* __restrict__ src, float* __restrict__ dst) {
    int i = blockIdx.x * blockDim.x + threadIdx.x;
    if (i < NPAD) dst[i] = (i < V_) ? src[i] : -1e30f;
}

__global__ void zero_f(float* p, size_t n) {
    size_t i = (size_t)blockIdx.x * blockDim.x + threadIdx.x;
    if (i < n) p[i] = 0.0f;
}

__global__ void zero_w(uint32_t* p, size_t n) {
    size_t i = (size_t)blockIdx.x * blockDim.x + threadIdx.x;
    if (i < n) p[i] = 0u;
}

__global__ void gather_split(const float* __restrict__ emb, const int* __restrict__ tok,
                             int isStart, bf16* __restrict__ wact) {
    int b = blockIdx.x;
    int t = isStart ? tok[0] : tok[b];
    size_t o = (size_t)b * KP_GATE;
    for (int c = threadIdx.x; c < E_; c += 128) {
        bf16 h, l; split2(emb[(size_t)t * E_ + c], h, l);
        wact[o + c] = h; wact[o + KCAT + c] = h; wact[o + 2 * KCAT + c] = l;
    }
}

// fused: combine argmax partials -> msg[b], then gather emb_s -> wact AND emb_r -> wact2
__global__ void argmax_gather(const float* __restrict__ pmax, const int* __restrict__ pidx,
                              int nt, int* __restrict__ msg,
                              const float* __restrict__ embS, bf16* __restrict__ wact,
                              const float* __restrict__ embR, bf16* __restrict__ wact2) {
    int b = blockIdx.x, tid = threadIdx.x, lane = tid & 31;
    __shared__ int stok;
    if (tid < 32) {
        float v = -3.4e38f; int ix = 0x7fffffff;
        for (int t = lane; t < nt; t += 32) {
            float vv = pmax[(size_t)b * NTPAD + t];
            int ii = pidx[(size_t)b * NTPAD + t];
            if (vv > v || (vv == v && ii < ix)) { v = vv; ix = ii; }
        }
#pragma unroll
        for (int o = 16; o > 0; o >>= 1) {
            float vo = __shfl_xor_sync(~0u, v, o); int io = __shfl_xor_sync(~0u, ix, o);
            if (vo > v || (vo == v && io < ix)) { v = vo; ix = io; }
        }
        if (!lane) { msg[b] = ix; stok = ix; }
    }
    __syncthreads();
    int t = stok;
    size_t o = (size_t)b * KP_GATE;
    for (int c = tid; c < E_; c += 128) {
        bf16 h, l;
        split2(embS[(size_t)t * E_ + c], h, l);
        wact[o + c] = h; wact[o + KCAT + c] = h; wact[o + 2 * KCAT + c] = l;
        split2(embR[(size_t)t * E_ + c], h, l);
        wact2[o + c] = h; wact2[o + KCAT + c] = h; wact2[o + 2 * KCAT + c] = l;
    }
}

// combine lse partials: msg + logprob for the last step
__global__ void lse_combine(const float* __restrict__ pmax, const int* __restrict__ pidx,
                            const float* __restrict__ psum, int nt,
                            int* __restrict__ msg, float* __restrict__ logprob) {
    int b = blockIdx.x, lane = threadIdx.x;
    float v = -3.4e38f; int ix = 0x7fffffff;
    for (int t = lane; t < nt; t += 32) {
        float vv = pmax[(size_t)b * NTPAD + t];
        int ii = pidx[(size_t)b * NTPAD + t];
        if (vv > v || (vv == v && ii < ix)) { v = vv; ix = ii; }
    }
#pragma unroll
    for (int o = 16; o > 0; o >>= 1) {
        float vo = __shfl_xor_sync(~0u, v, o); int io = __shfl_xor_sync(~0u, ix, o);
        if (vo > v || (vo == v && io < ix)) { v = vo; ix = io; }
    }
    float S = 0.f;
    for (int t = lane; t < nt; t += 32) {
        float sw = psum[(size_t)b * NTPAD + t];
        if (sw > 0.f) S += sw * expf(pmax[(size_t)b * NTPAD + t] - v);
    }
#pragma unroll
    for (int o = 16; o > 0; o >>= 1) S += __shfl_xor_sync(~0u, S, o);
    if (!lane) { msg[b] = ix; logprob[b] = -logf(S); }
}

__global__ void hsplit_wact(const float* __restrict__ src,
                            bf16* __restrict__ hdup, bf16* __restrict__ wact) {
    int idx = blockIdx.x * blockDim.x + threadIdx.x;
    if (idx >= B_ * H_) return;
    int b = idx >> 10, j = idx & (H_ - 1);
    bf16 h, l; split2(src[idx], h, l);
    size_t oh = (size_t)b * KP_LOG;
    hdup[oh + j] = h; hdup[oh + H_ + j] = h; hdup[oh + 2 * H_ + j] = l;
    size_t ow = (size_t)b * KP_GATE + E_;
    wact[ow + j] = h; wact[ow + KCAT + j] = h; wact[ow + 2 * KCAT + j] = l;
}

__global__ void rsplit(const float* __restrict__ src, bf16* __restrict__ dst) {
    int idx = blockIdx.x * blockDim.x + threadIdx.x;
    if (idx >= B_ * F_) return;
    int b = idx >> 12, k = idx & (F_ - 1);
    bf16 h, l; split2(src[idx], h, l);
    size_t base = (size_t)b * KP_TS;
    dst[base + k] = h; dst[base + F_ + k] = l; dst[base + 2 * F_ + k] = h;
}

__global__ void reduce_rows(const float* __restrict__ sc, const float* __restrict__ lp,
                            float* __restrict__ lsum, float* __restrict__ tp,
                            float* __restrict__ dp) {
    int b = blockIdx.x, tid = threadIdx.x;
    float l = 0.f, t = 0.f, d0 = 0.f, d1 = 0.f, d2 = 0.f, d3 = 0.f;
    const float* tsr = sc + (size_t)b * B_;
    const float* dr0 = sc + (size_t)(1024 + b) * B_;
    const float* dr1 = sc + (size_t)(2048 + b) * B_;
    const float* dr2 = sc + (size_t)(3072 + b) * B_;
    const float* dr3 = sc + (size_t)(4096 + b) * B_;
    for (int k = tid; k < B_; k += 256) {
        float tv = tsr[k];
        float v0 = dr0[k], v1 = dr1[k], v2 = dr2[k], v3 = dr3[k];
        float h = fmaxf(0.f, 1.f - tv + v0) + fmaxf(0.f, 1.f - tv + v1)
                + fmaxf(0.f, 1.f - tv + v2) + fmaxf(0.f, 1.f - tv + v3);
        l += h * lp[k];
        t += expf(tv);
        d0 += expf(v0); d1 += expf(v1); d2 += expf(v2); d3 += expf(v3);
    }
    __shared__ float sh[6][256];
    sh[0][tid] = l; sh[1][tid] = t; sh[2][tid] = d0;
    sh[3][tid] = d1; sh[4][tid] = d2; sh[5][tid] = d3;
    __syncthreads();
    for (int s = 128; s > 0; s >>= 1) {
        if (tid < s)
            for (int q = 0; q < 6; q++) sh[q][tid] += sh[q][tid + s];
        __syncthreads();
    }
    if (tid == 0) {
        lsum[b] = sh[0][0]; tp[b] = sh[1][0];
        dp[b] = sh[2][0]; dp[B_ + b] = sh[3][0];
        dp[2 * B_ + b] = sh[4][0]; dp[3 * B_ + b] = sh[5][0];
    }
}

__global__ void finalize(const float* __restrict__ lsum, const float* __restrict__ tp,
                         const float* __restrict__ dp, float* __restrict__ out) {
    int tid = threadIdx.x;
    float lo = 0.f, an = 0.f;
    for (int b = tid; b < B_; b += 256) {
        lo += lsum[b];
        float t = tp[b];
        bool ok = (t >= dp[b]) && (t >= dp[B_ + b]) &&
                  (t >= dp[2 * B_ + b]) && (t >= dp[3 * B_ + b]);
        an += ok ? 1.0f : 0.0f;
    }
    __shared__ float s0[256], s1[256];
    s0[tid] = lo; s1[tid] = an;
    __syncthreads();
    for (int s = 128; s > 0; s >>= 1) {
        if (tid < s) { s0[tid] += s0[tid + s]; s1[tid] += s1[tid + s]; }
        __syncthreads();
    }
    if (tid == 0) {
        out[0] = -s0[0] / ((float)B_ * (float)B_);
        out[1] = s1[0] / (float)B_;
    }
}

// ---------------- host ----------------
#define SYM(p, g) cudaGetSymbolAddress((void**)&p, g)
static inline size_t gb1(size_t n) { return (n + 255) / 256; }
static inline size_t gb2(size_t n) { return (n / 2 + 255) / 256; }

extern "C" void kernel_launch(void* const* d_in, const int* in_sizes, int n_in,
                              void* d_out, int out_size) {
    (void)in_sizes; (void)n_in; (void)out_size;
    const float* target      = (const float*)d_in[0];
    const float* distractors = (const float*)d_in[1];
    const int*   start_tok   = (const int*)d_in[2];
    const float* emb_s   = (const float*)d_in[4];
    const float* Wih_s   = (const float*)d_in[5];
    const float* Whh_s   = (const float*)d_in[6];
    const float* bih_s   = (const float*)d_in[7];
    const float* bhh_s   = (const float*)d_in[8];
    const float* aff_s_W = (const float*)d_in[9];
    const float* aff_s_b = (const float*)d_in[10];
    const float* probs_W = (const float*)d_in[11];
    const float* probs_b = (const float*)d_in[12];
    const float* emb_r   = (const float*)d_in[13];
    const float* Wih_r   = (const float*)d_in[14];
    const float* Whh_r   = (const float*)d_in[15];
    const float* bih_r   = (const float*)d_in[16];
    const float* bhh_r   = (const float*)d_in[17];
    const float* aff_r_W = (const float*)d_in[18];
    const float* aff_r_b = (const float*)d_in[19];
    float* out = (float*)d_out;

    bf16 *pProbs, *pWcS, *pWcR, *pAfS, *pAfR, *pA5, *pRd, *pWa, *pWa2, *pHd, *pHd2;
    float *pHf, *pC, *pC2, *pG, *pG2, *pRf, *pSc, *pLp;
    float *pBs, *pBr, *pPb, *pLs, *pTp, *pDp, *pPm, *pPs;
    int *pMsg, *pPi;
    SYM(pProbs, d_probs); SYM(pWcS, d_wcat_s); SYM(pWcR, d_wcat_r);
    SYM(pAfS, d_affs); SYM(pAfR, d_affr); SYM(pA5, d_a5); SYM(pRd, d_rdup);
    SYM(pWa, d_wact); SYM(pWa2, d_wact2); SYM(pHd, d_hdup); SYM(pHd2, d_hdup2);
    SYM(pHf, g_hf); SYM(pC, g_c); SYM(pC2, g_c2); SYM(pG, g_gates); SYM(pG2, g_gates2);
    SYM(pRf, g_rf); SYM(pSc, g_sc); SYM(pLp, g_logprob);
    SYM(pBs, g_bias_s); SYM(pBr, g_bias_r); SYM(pPb, g_pbias);
    SYM(pLs, g_lsum); SYM(pTp, g_tp); SYM(pDp, g_dp); SYM(pMsg, g_msg);
    SYM(pPm, g_pmax); SYM(pPi, g_pidx); SYM(pPs, g_psum);

    cudaFuncSetAttribute(gemm_bf16<0>, cudaFuncAttributeMaxDynamicSharedMemorySize, SMEM_G);
    cudaFuncSetAttribute(gemm_bf16<1>, cudaFuncAttributeMaxDynamicSharedMemorySize, SMEM_G);
    cudaFuncSetAttribute(gemm_bf16<2>, cudaFuncAttributeMaxDynamicSharedMemorySize, SMEM_G);

    // ---- prep ----
    add_vec_perm<<<(G4H + 255) / 256, 256>>>(bih_s, bhh_s, pBs);
    add_vec_perm<<<(G4H + 255) / 256, 256>>>(bih_r, bhh_r, pBr);
    pad_bias<<<(NPAD + 255) / 256, 256>>>(probs_b, pPb);
    split_dupA2<<<gb2((size_t)B_ * F_), 256>>>(target, pA5, F_, (size_t)B_ * F_);
    split_dupA2<<<gb2((size_t)D_ * B_ * F_), 256>>>(distractors, pA5 + (size_t)B_ * KP_TS,
                                                    F_, (size_t)D_ * B_ * F_);
    split_dupB2<<<gb2((size_t)H_ * F_), 256>>>(aff_s_W, pAfS, F_, (size_t)H_ * F_);
    split_dupB2<<<gb2((size_t)F_ * H_), 256>>>(aff_r_W, pAfR, H_, (size_t)F_ * H_);
    split_dupB_pad2<<<gb2((size_t)NPAD * H_), 256>>>(probs_W, pProbs, V_, NPAD, H_);
    split_cat_perm2<<<gb2((size_t)G4H * KCAT), 256>>>(Wih_s, Whh_s, pWcS, E_, H_);
    split_cat_perm2<<<gb2((size_t)G4H * KCAT), 256>>>(Wih_r, Whh_r, pWcR, E_, H_);

    // ---- init ----
    zero_f<<<gb1((size_t)B_ * H_), 256>>>(pC, (size_t)B_ * H_);
    zero_f<<<gb1((size_t)B_ * H_), 256>>>(pC2, (size_t)B_ * H_);
    zero_w<<<gb1((size_t)B_ * KP_GATE / 2), 256>>>((uint32_t*)pWa2, (size_t)B_ * KP_GATE / 2);
    gemm_bf16<0><<<dim3(8, 8, 1), 256, SMEM_G>>>(pA5, pAfS, aff_s_b, pHf, KP_TS, H_, 0,
                                                 nullptr, nullptr, nullptr,
                                                 nullptr, nullptr, nullptr, nullptr);
    hsplit_wact<<<gb1((size_t)B_ * H_), 256>>>(pHf, pHd, pWa);
    gather_split<<<B_, 128>>>(emb_s, start_tok, 1, pWa);

    // ---- main loop: sender step s; receiver step s-1 rides along (z=2) ----
    for (int s = 0; s < L_; s++) {
        int dual = (s >= 1);
        if (dual) {
            gemm_bf16<0><<<dim3(8, 32, 2), 256, SMEM_G>>>(pWa, pWcS, pBs, pG, KP_GATE, G4H, 0,
                                                          nullptr, nullptr, nullptr,
                                                          pWa2, pWcR, pBr, pG2);
            lstm_split_packed<<<gb1(2 * (size_t)B_ * H_), 256>>>(pG, pC, pHd, pWa,
                                                                 pG2, pC2, pHd2, pWa2,
                                                                 2 * B_ * H_);
        } else {
            gemm_bf16<0><<<dim3(8, 32, 1), 256, SMEM_G>>>(pWa, pWcS, pBs, pG, KP_GATE, G4H, 0,
                                                          nullptr, nullptr, nullptr,
                                                          nullptr, nullptr, nullptr, nullptr);
            lstm_split_packed<<<gb1((size_t)B_ * H_), 256>>>(pG, pC, pHd, pWa,
                                                             nullptr, nullptr, nullptr, nullptr,
                                                             B_ * H_);
        }
        if (s < L_ - 1) {
            gemm_bf16<1><<<dim3(8, 157, 1), 256, SMEM_G>>>(pHd, pProbs, pPb, nullptr, KP_LOG,
                                                           NPAD, 0, pPm, pPi, nullptr,
                                                           nullptr, nullptr, nullptr, nullptr);
            argmax_gather<<<B_, 128>>>(pPm, pPi, 157, pMsg + s * B_, emb_s, pWa, emb_r, pWa2);
        } else {
            gemm_bf16<2><<<dim3(8, 157, 1), 256, SMEM_G>>>(pHd, pProbs, pPb, nullptr, KP_LOG,
                                                           NPAD, 0, pPm, pPi, pPs,
                                                           nullptr, nullptr, nullptr, nullptr);
            lse_combine<<<B_, 32>>>(pPm, pPi, pPs, 157, pMsg + s * B_, pLp);
        }
    }

    // ---- receiver final step (r = L-1) ----
    gather_split<<<B_, 128>>>(emb_r, pMsg + (L_ - 1) * B_, 0, pWa2);
    gemm_bf16<0><<<dim3(8, 32, 1), 256, SMEM_G>>>(pWa2, pWcR, pBr, pG2, KP_GATE, G4H, 0,
                                                  nullptr, nullptr, nullptr,
                                                  nullptr, nullptr, nullptr, nullptr);
    lstm_split_packed<<<gb1((size_t)B_ * H_), 256>>>(pG2, pC2, pHd2, pWa2,
                                                     nullptr, nullptr, nullptr, nullptr,
                                                     B_ * H_);

    // ---- r, ts/ds, loss ----
    gemm_bf16<0><<<dim3(8, 32, 1), 256, SMEM_G>>>(pHd2, pAfR, aff_r_b, pRf, KP_LOG, F_, 0,
                                                  nullptr, nullptr, nullptr,
                                                  nullptr, nullptr, nullptr, nullptr);
    rsplit<<<gb1((size_t)B_ * F_), 256>>>(pRf, pRd);
    gemm_bf16<0><<<dim3(8, 40, 1), 256, SMEM_G>>>(pA5, pRd, nullptr, pSc, KP_TS, B_, 1,
                                                  nullptr, nullptr, nullptr,
                                                  nullptr, nullptr, nullptr, nullptr);
    reduce_rows<<<B_, 256>>>(pSc, pLp, pLs, pTp, pDp);
    finalize<<<1, 256>>>(pLs, pTp, pDp, out);
}

// round 17
// speedup vs baseline: 1.2098x; 1.0344x over previous
#include <cuda_runtime.h>
#include <cuda_bf16.h>
#include <math.h>
#include <stdint.h>

#define B_ 1024
#define F_ 4096
#define V_ 20000
#define NPAD 20096
#define E_ 512
#define H_ 1024
#define L_ 20
#define D_ 4
#define G4H 4096
#define KCAT 1536
#define KP_GATE (3*KCAT)   // 4608
#define KP_LOG  (3*H_)     // 3072
#define KP_TS   (3*F_)     // 12288
#define NTPAD 160

typedef __nv_bfloat16 bf16;

// ---------------- scratch ----------------
__device__ __align__(256) bf16 d_probs[(size_t)NPAD*KP_LOG];
__device__ __align__(256) bf16 d_wcat_s[(size_t)G4H*KP_GATE];
__device__ __align__(256) bf16 d_wcat_r[(size_t)G4H*KP_GATE];
__device__ __align__(256) bf16 d_affs[(size_t)H_*KP_TS];
__device__ __align__(256) bf16 d_affr[(size_t)F_*KP_LOG];
__device__ __align__(256) bf16 d_a5[(size_t)5*B_*KP_TS];
__device__ __align__(256) bf16 d_rdup[(size_t)B_*KP_TS];
__device__ __align__(256) bf16 d_wact[(size_t)B_*KP_GATE];     // sender activations
__device__ __align__(256) bf16 d_wact2[(size_t)B_*KP_GATE];    // receiver activations
__device__ __align__(256) bf16 d_hdup[(size_t)B_*KP_LOG];      // sender h
__device__ __align__(256) bf16 d_hdup2[(size_t)B_*KP_LOG];     // receiver h

__device__ __align__(256) float g_hf[B_*H_];
__device__ __align__(256) float g_c[B_*H_];
__device__ __align__(256) float g_c2[B_*H_];
__device__ __align__(256) float g_gates[(size_t)B_*G4H];
__device__ __align__(256) float g_gates2[(size_t)B_*G4H];
__device__ __align__(256) float g_rf[(size_t)B_*F_];
__device__ __align__(256) float g_sc[(size_t)5*B_*B_];
__device__ __align__(256) float g_pmax[(size_t)B_*NTPAD];
__device__ __align__(256) float g_psum[(size_t)B_*NTPAD];
__device__ __align__(256) int   g_pidx[(size_t)B_*NTPAD];
__device__ int   g_msg[L_*B_];
__device__ float g_logprob[B_];
__device__ float g_bias_s[G4H];
__device__ float g_bias_r[G4H];
__device__ float g_pbias[NPAD];
__device__ float g_lsum[B_];
__device__ float g_tp[B_];
__device__ float g_dp[D_*B_];

// ---------------- helpers ----------------
__device__ __forceinline__ uint32_t smem_u32(const void* p) {
    uint32_t a;
    asm("{ .reg .u64 t; cvta.to.shared.u64 t, %1; cvt.u32.u64 %0, t; }" : "=r"(a) : "l"(p));
    return a;
}
__device__ __forceinline__ void split2(float x, bf16& h, bf16& l) {
    h = __float2bfloat16(x);
    l = __float2bfloat16(x - __bfloat162float(h));
}
__device__ __forceinline__ float sigf(float x) { return 1.0f / (1.0f + expf(-x)); }

// ---------------- bf16 NT GEMM via mma.sync (BM=128, BN=128, 256 thr, 2 CTA/SM) ----------------
// MODE: 0 = store C (+bias), 1 = argmax partials, 2 = argmax + logsumexp partials
// z==1 plane: independent second GEMM (A2/B2/bias2/C2, Kp2/Ncols2, y < yT2), store epilogue.
#define STAGE_BYTES 32768
#define SMEM_G (3*STAGE_BYTES)

template<int MODE>
__global__ void __launch_bounds__(256, 2)
gemm_bf16(const bf16* __restrict__ A, const bf16* __restrict__ Bw,
          const float* __restrict__ bias, float* __restrict__ C,
          int Kp, int Ncols, int swapRaster,
          float* __restrict__ pmax, int* __restrict__ pidx, float* __restrict__ psum,
          const bf16* __restrict__ A2, const bf16* __restrict__ B2,
          const float* __restrict__ bias2, float* __restrict__ C2,
          int Kp2, int Ncols2, int yT2)
{
    extern __shared__ char smem_[];
    const uint32_t sbase = smem_u32(smem_);
    bool storeEpi = (MODE == 0);
    if (blockIdx.z == 1) {
        if ((int)blockIdx.y >= yT2) return;
        A = A2; Bw = B2; bias = bias2; C = C2; Kp = Kp2; Ncols = Ncols2;
        storeEpi = true;
    }
    int bm, bn;
    if (swapRaster) { bm = blockIdx.y * 128; bn = blockIdx.x * 128; }
    else            { bm = blockIdx.x * 128; bn = blockIdx.y * 128; }
    const int tid = threadIdx.x, lane = tid & 31, wid = tid >> 5;
    const int wm = wid >> 2, wn = wid & 3;

    const char* Ag = (const char*)(A + (size_t)bm * Kp);
    const char* Bg = (const char*)(Bw + (size_t)bn * Kp);
    const size_t rowB = (size_t)Kp * 2;
    const int nk = Kp >> 6;

    auto loadTile = [&](int ck, int st) {
        uint32_t sp = sbase + st * STAGE_BYTES;
        size_t ko = (size_t)ck * 128;
#pragma unroll
        for (int h = 0; h < 2; h++) {
            const char* G = (h ? Bg : Ag) + ko;
            uint32_t S = sp + h * 16384;
#pragma unroll
            for (int it = 0; it < 4; it++) {
                int r = it * 32 + (tid >> 3);
                int s = tid & 7;
                uint32_t sa = S + (uint32_t)r * 128 + ((s ^ (r & 7)) * 16);
                const char* ga = G + (size_t)r * rowB + s * 16;
                asm volatile("cp.async.cg.shared.global [%0], [%1], 16;" :: "r"(sa), "l"(ga));
            }
        }
        asm volatile("cp.async.commit_group;" ::: "memory");
    };

    float acc[4][4][4];
#pragma unroll
    for (int a = 0; a < 4; a++)
#pragma unroll
        for (int b = 0; b < 4; b++)
#pragma unroll
            for (int q = 0; q < 4; q++) acc[a][b][q] = 0.0f;

    loadTile(0, 0);
    if (nk > 1) loadTile(1, 1);

    for (int i = 0; i < nk; i++) {
        if (i + 1 < nk) asm volatile("cp.async.wait_group 1;" ::: "memory");
        else            asm volatile("cp.async.wait_group 0;" ::: "memory");
        __syncthreads();
        uint32_t Ab = sbase + (i % 3) * STAGE_BYTES;
        uint32_t Bb = Ab + 16384;
#pragma unroll
        for (int j = 0; j < 4; j++) {
            uint32_t af[4][4], bfr[2][4];
            int ar = lane & 15;
            int asel = 2 * j + (lane >> 4);
#pragma unroll
            for (int mi = 0; mi < 4; mi++) {
                int row = wm * 64 + mi * 16 + ar;
                uint32_t ad = Ab + row * 128 + ((asel ^ (row & 7)) * 16);
                asm volatile("ldmatrix.sync.aligned.m8n8.x4.shared.b16 {%0,%1,%2,%3}, [%4];"
                    : "=r"(af[mi][0]), "=r"(af[mi][1]), "=r"(af[mi][2]), "=r"(af[mi][3])
                    : "r"(ad));
            }
            int bsel = 2 * j + ((lane >> 3) & 1);
#pragma unroll
            for (int p = 0; p < 2; p++) {
                int nr = wn * 32 + (p * 2 + (lane >> 4)) * 8 + (lane & 7);
                uint32_t bd = Bb + nr * 128 + ((bsel ^ (nr & 7)) * 16);
                asm volatile("ldmatrix.sync.aligned.m8n8.x4.shared.b16 {%0,%1,%2,%3}, [%4];"
                    : "=r"(bfr[p][0]), "=r"(bfr[p][1]), "=r"(bfr[p][2]), "=r"(bfr[p][3])
                    : "r"(bd));
            }
#pragma unroll
            for (int mi = 0; mi < 4; mi++)
#pragma unroll
                for (int ni = 0; ni < 4; ni++) {
                    uint32_t b0 = bfr[ni >> 1][(ni & 1) * 2];
                    uint32_t b1 = bfr[ni >> 1][(ni & 1) * 2 + 1];
                    asm volatile(
                        "mma.sync.aligned.m16n8k16.row.col.f32.bf16.bf16.f32 "
                        "{%0,%1,%2,%3}, {%4,%5,%6,%7}, {%8,%9}, {%0,%1,%2,%3};"
                        : "+f"(acc[mi][ni][0]), "+f"(acc[mi][ni][1]),
                          "+f"(acc[mi][ni][2]), "+f"(acc[mi][ni][3])
                        : "r"(af[mi][0]), "r"(af[mi][1]), "r"(af[mi][2]), "r"(af[mi][3]),
                          "r"(b0), "r"(b1));
                }
        }
        if (i + 2 < nk) loadTile(i + 2, (i + 2) % 3);
    }

    if (storeEpi) {
#pragma unroll
        for (int mi = 0; mi < 4; mi++) {
            int row = bm + wm * 64 + mi * 16 + (lane >> 2);
#pragma unroll
            for (int ni = 0; ni < 4; ni++) {
                int col = bn + wn * 32 + ni * 8 + (lane & 3) * 2;
                float b0 = bias ? bias[col] : 0.0f;
                float b1 = bias ? bias[col + 1] : 0.0f;
                float2 v;
                v.x = acc[mi][ni][0] + b0; v.y = acc[mi][ni][1] + b1;
                *(float2*)&C[(size_t)row * Ncols + col] = v;
                v.x = acc[mi][ni][2] + b0; v.y = acc[mi][ni][3] + b1;
                *(float2*)&C[(size_t)(row + 8) * Ncols + col] = v;
            }
        }
    } else {
        __syncthreads();
        float* smax = (float*)smem_;
        int*   sidx = (int*)(smem_ + 2048);
        float* ssum = (float*)(smem_ + 4096);
#pragma unroll
        for (int mi = 0; mi < 4; mi++) {
            float mv0 = -3.4e38f, mv1 = -3.4e38f;
            int ix0 = V_, ix1 = V_;
#pragma unroll
            for (int ni = 0; ni < 4; ni++) {
                int colb = bn + wn * 32 + ni * 8 + (lane & 3) * 2;
                float bb0 = bias[colb], bb1 = bias[colb + 1];
                float v;
                if (colb < V_) {
                    v = acc[mi][ni][0] + bb0; if (v > mv0) { mv0 = v; ix0 = colb; }
                    v = acc[mi][ni][2] + bb0; if (v > mv1) { mv1 = v; ix1 = colb; }
                }
                if (colb + 1 < V_) {
                    v = acc[mi][ni][1] + bb1; if (v > mv0) { mv0 = v; ix0 = colb + 1; }
                    v = acc[mi][ni][3] + bb1; if (v > mv1) { mv1 = v; ix1 = colb + 1; }
                }
            }
#pragma unroll
            for (int o = 1; o < 4; o <<= 1) {
                float vo = __shfl_xor_sync(~0u, mv0, o); int io = __shfl_xor_sync(~0u, ix0, o);
                if (vo > mv0 || (vo == mv0 && io < ix0)) { mv0 = vo; ix0 = io; }
                vo = __shfl_xor_sync(~0u, mv1, o); io = __shfl_xor_sync(~0u, ix1, o);
                if (vo > mv1 || (vo == mv1 && io < ix1)) { mv1 = vo; ix1 = io; }
            }
            float s0 = 0.f, s1 = 0.f;
            if (MODE == 2) {
#pragma unroll
                for (int ni = 0; ni < 4; ni++) {
                    int colb = bn + wn * 32 + ni * 8 + (lane & 3) * 2;
                    float bb0 = bias[colb], bb1 = bias[colb + 1];
                    if (colb < V_) {
                        s0 += expf(acc[mi][ni][0] + bb0 - mv0);
                        s1 += expf(acc[mi][ni][2] + bb0 - mv1);
                    }
                    if (colb + 1 < V_) {
                        s0 += expf(acc[mi][ni][1] + bb1 - mv0);
                        s1 += expf(acc[mi][ni][3] + bb1 - mv1);
                    }
                }
#pragma unroll
                for (int o = 1; o < 4; o <<= 1) {
                    s0 += __shfl_xor_sync(~0u, s0, o);
                    s1 += __shfl_xor_sync(~0u, s1, o);
                }
            }
            if ((lane & 3) == 0) {
                int lr = wm * 64 + mi * 16 + (lane >> 2);
                smax[lr * 4 + wn] = mv0; sidx[lr * 4 + wn] = ix0;
                smax[(lr + 8) * 4 + wn] = mv1; sidx[(lr + 8) * 4 + wn] = ix1;
                if (MODE == 2) { ssum[lr * 4 + wn] = s0; ssum[(lr + 8) * 4 + wn] = s1; }
            }
        }
        __syncthreads();
        if (tid < 128) {
            float v = -3.4e38f; int ix = V_;
#pragma unroll
            for (int w = 0; w < 4; w++) {
                float vv = smax[tid * 4 + w]; int ii = sidx[tid * 4 + w];
                if (vv > v || (vv == v && ii < ix)) { v = vv; ix = ii; }
            }
            int gnt = swapRaster ? blockIdx.x : blockIdx.y;
            pmax[(size_t)(bm + tid) * NTPAD + gnt] = v;
            pidx[(size_t)(bm + tid) * NTPAD + gnt] = ix;
            if (MODE == 2) {
                float S = 0.f;
#pragma unroll
                for (int w = 0; w < 4; w++) {
                    float sw = ssum[tid * 4 + w];
                    if (sw > 0.f) S += sw * expf(smax[tid * 4 + w] - v);
                }
                psum[(size_t)(bm + tid) * NTPAD + gnt] = S;
            }
        }
    }
}

// ---------------- LSTM pointwise single (gates packed col=4j+gate) ----------------
__global__ void lstm_split_packed(const float* __restrict__ gates, float* __restrict__ c,
                                  bf16* __restrict__ hdup, bf16* __restrict__ wact) {
    int idx = blockIdx.x * blockDim.x + threadIdx.x;
    if (idx >= B_ * H_) return;
    int b = idx >> 10, j = idx & (H_ - 1);
    float4 g = *(const float4*)(gates + (size_t)b * G4H + 4 * j);
    float cn = sigf(g.y) * c[idx] + sigf(g.x) * tanhf(g.z);
    c[idx] = cn;
    float hv = sigf(g.w) * tanhf(cn);
    bf16 h, l; split2(hv, h, l);
    size_t oh = (size_t)b * KP_LOG;
    hdup[oh + j] = h; hdup[oh + H_ + j] = h; hdup[oh + 2 * H_ + j] = l;
    size_t ow = (size_t)b * KP_GATE + E_;
    wact[ow + j] = h; wact[ow + KCAT + j] = h; wact[ow + 2 * KCAT + j] = l;
}

// ---------------- prep kernels ----------------
__global__ void split_dupA2(const float* __restrict__ src, bf16* __restrict__ dst,
                            int K, size_t n) {
    size_t i = ((size_t)blockIdx.x * blockDim.x + threadIdx.x) * 2;
    if (i >= n) return;
    size_t r = i / K; int k = (int)(i % K);
    float2 v = *(const float2*)(src + i);
    bf16 h0, l0, h1, l1; split2(v.x, h0, l0); split2(v.y, h1, l1);
    __nv_bfloat162 H2, L2; H2.x = h0; H2.y = h1; L2.x = l0; L2.y = l1;
    size_t base = r * (size_t)(3 * K) + k;
    *(__nv_bfloat162*)(dst + base) = H2;
    *(__nv_bfloat162*)(dst + base + K) = H2;
    *(__nv_bfloat162*)(dst + base + 2 * K) = L2;
}

__global__ void split_dupB2(const float* __restrict__ src, bf16* __restrict__ dst,
                            int K, size_t n) {
    size_t i = ((size_t)blockIdx.x * blockDim.x + threadIdx.x) * 2;
    if (i >= n) return;
    size_t r = i / K; int k = (int)(i % K);
    float2 v = *(const float2*)(src + i);
    bf16 h0, l0, h1, l1; split2(v.x, h0, l0); split2(v.y, h1, l1);
    __nv_bfloat162 H2, L2; H2.x = h0; H2.y = h1; L2.x = l0; L2.y = l1;
    size_t base = r * (size_t)(3 * K) + k;
    *(__nv_bfloat162*)(dst + base) = H2;
    *(__nv_bfloat162*)(dst + base + K) = L2;
    *(__nv_bfloat162*)(dst + base + 2 * K) = H2;
}

__global__ void split_dupB_pad2(const float* __restrict__ src, bf16* __restrict__ dst,
                                int srcRows, int dstRows, int K) {
    size_t i = ((size_t)blockIdx.x * blockDim.x + threadIdx.x) * 2;
    if (i >= (size_t)dstRows * K) return;
    size_t r = i / K; int k = (int)(i % K);
    float2 v = make_float2(0.f, 0.f);
    if (r < (size_t)srcRows) v = *(const float2*)(src + r * K + k);
    bf16 h0, l0, h1, l1; split2(v.x, h0, l0); split2(v.y, h1, l1);
    __nv_bfloat162 H2, L2; H2.x = h0; H2.y = h1; L2.x = l0; L2.y = l1;
    size_t base = r * (size_t)(3 * K) + k;
    *(__nv_bfloat162*)(dst + base) = H2;
    *(__nv_bfloat162*)(dst + base + K) = L2;
    *(__nv_bfloat162*)(dst + base + 2 * K) = H2;
}

__global__ void split_cat_perm2(const float* __restrict__ W1, const float* __restrict__ W2,
                                bf16* __restrict__ dst, int c1, int c2) {
    int K = c1 + c2;
    size_t i = ((size_t)blockIdx.x * blockDim.x + threadIdx.x) * 2;
    if (i >= (size_t)G4H * K) return;
    size_t r = i / K; int k = (int)(i % K);
    size_t rs = (size_t)((r & 3) * H_ + (r >> 2));
    float2 v = (k < c1) ? *(const float2*)(W1 + rs * c1 + k)
                        : *(const float2*)(W2 + rs * c2 + (k - c1));
    bf16 h0, l0, h1, l1; split2(v.x, h0, l0); split2(v.y, h1, l1);
    __nv_bfloat162 H2, L2; H2.x = h0; H2.y = h1; L2.x = l0; L2.y = l1;
    size_t base = r * (size_t)(3 * K) + k;
    *(__nv_bfloat162*)(dst + base) = H2;
    *(__nv_bfloat162*)(dst + base + K) = L2;
    *(__nv_bfloat162*)(dst + base + 2 * K) = H2;
}

__global__ void add_vec_perm(const float* a, const float* b, float* o) {
    int n = blockIdx.x * blockDim.x + threadIdx.x;
    if (n < G4H) {
        int s = (n & 3) * H_ + (n >> 2);
        o[n] = a[s] + b[s];
    }
}

__global__ void pad_bias(const float* __restrict__ src, float* __restrict__ dst) {
    int i = blockIdx.x * blockDim.x + threadIdx.x;
    if (i < NPAD) dst[i] = (i < V_) ? src[i] : -1e30f;
}

__global__ void zero_f(float* p, size_t n) {
    size_t i = (size_t)blockIdx.x * blockDim.x + threadIdx.x;
    if (i < n) p[i] = 0.0f;
}

__global__ void zero_w(uint32_t* p, size_t n) {
    size_t i = (size_t)blockIdx.x * blockDim.x + threadIdx.x;
    if (i < n) p[i] = 0u;
}

__global__ void gather_split(const float* __restrict__ emb, const int* __restrict__ tok,
                             int isStart, bf16* __restrict__ wact) {
    int b = blockIdx.x;
    int t = isStart ? tok[0] : tok[b];
    size_t o = (size_t)b * KP_GATE;
    for (int c = threadIdx.x; c < E_; c += 128) {
        bf16 h, l; split2(emb[(size_t)t * E_ + c], h, l);
        wact[o + c] = h; wact[o + KCAT + c] = h; wact[o + 2 * KCAT + c] = l;
    }
}

// fused: argmax combine -> msg; gather emb_s->wact, emb_r->wact2; optional recv LSTM step
__global__ void argmax_gather(const float* __restrict__ pmax, const int* __restrict__ pidx,
                              int nt, int* __restrict__ msg,
                              const float* __restrict__ embS, bf16* __restrict__ wact,
                              const float* __restrict__ embR, bf16* __restrict__ wact2,
                              const float* __restrict__ gates2, float* __restrict__ c2,
                              bf16* __restrict__ hdup2, int doLstm) {
    int b = blockIdx.x, tid = threadIdx.x, lane = tid & 31;
    __shared__ int stok;
    if (tid < 32) {
        float v = -3.4e38f; int ix = 0x7fffffff;
        for (int t = lane; t < nt; t += 32) {
            float vv = pmax[(size_t)b * NTPAD + t];
            int ii = pidx[(size_t)b * NTPAD + t];
            if (vv > v || (vv == v && ii < ix)) { v = vv; ix = ii; }
        }
#pragma unroll
        for (int o = 16; o > 0; o >>= 1) {
            float vo = __shfl_xor_sync(~0u, v, o); int io = __shfl_xor_sync(~0u, ix, o);
            if (vo > v || (vo == v && io < ix)) { v = vo; ix = io; }
        }
        if (!lane) { msg[b] = ix; stok = ix; }
    }
    // receiver LSTM for this row (independent of the argmax result)
    if (doLstm) {
#pragma unroll
        for (int q = 0; q < 4; q++) {
            int j = tid * 4 + q;   // 256 thr * 4 = 1024
            float4 g = *(const float4*)(gates2 + (size_t)b * G4H + 4 * j);
            size_t ci = (size_t)b * H_ + j;
            float cn = sigf(g.y) * c2[ci] + sigf(g.x) * tanhf(g.z);
            c2[ci] = cn;
            float hv = sigf(g.w) * tanhf(cn);
            bf16 h, l; split2(hv, h, l);
            size_t oh = (size_t)b * KP_LOG;
            hdup2[oh + j] = h; hdup2[oh + H_ + j] = h; hdup2[oh + 2 * H_ + j] = l;
            size_t ow = (size_t)b * KP_GATE + E_;
            wact2[ow + j] = h; wact2[ow + KCAT + j] = h; wact2[ow + 2 * KCAT + j] = l;
        }
    }
    __syncthreads();
    int t = stok;
    size_t o = (size_t)b * KP_GATE;
    for (int c = tid; c < E_; c += 256) {
        bf16 h, l;
        split2(embS[(size_t)t * E_ + c], h, l);
        wact[o + c] = h; wact[o + KCAT + c] = h; wact[o + 2 * KCAT + c] = l;
        split2(embR[(size_t)t * E_ + c], h, l);
        wact2[o + c] = h; wact2[o + KCAT + c] = h; wact2[o + 2 * KCAT + c] = l;
    }
}

// combine lse partials: msg + logprob for the last step
__global__ void lse_combine(const float* __restrict__ pmax, const int* __restrict__ pidx,
                            const float* __restrict__ psum, int nt,
                            int* __restrict__ msg, float* __restrict__ logprob) {
    int b = blockIdx.x, lane = threadIdx.x;
    float v = -3.4e38f; int ix = 0x7fffffff;
    for (int t = lane; t < nt; t += 32) {
        float vv = pmax[(size_t)b * NTPAD + t];
        int ii = pidx[(size_t)b * NTPAD + t];
        if (vv > v || (vv == v && ii < ix)) { v = vv; ix = ii; }
    }
#pragma unroll
    for (int o = 16; o > 0; o >>= 1) {
        float vo = __shfl_xor_sync(~0u, v, o); int io = __shfl_xor_sync(~0u, ix, o);
        if (vo > v || (vo == v && io < ix)) { v = vo; ix = io; }
    }
    float S = 0.f;
    for (int t = lane; t < nt; t += 32) {
        float sw = psum[(size_t)b * NTPAD + t];
        if (sw > 0.f) S += sw * expf(pmax[(size_t)b * NTPAD + t] - v);
    }
#pragma unroll
    for (int o = 16; o > 0; o >>= 1) S += __shfl_xor_sync(~0u, S, o);
    if (!lane) { msg[b] = ix; logprob[b] = -logf(S); }
}

__global__ void hsplit_wact(const float* __restrict__ src,
                            bf16* __restrict__ hdup, bf16* __restrict__ wact) {
    int idx = blockIdx.x * blockDim.x + threadIdx.x;
    if (idx >= B_ * H_) return;
    int b = idx >> 10, j = idx & (H_ - 1);
    bf16 h, l; split2(src[idx], h, l);
    size_t oh = (size_t)b * KP_LOG;
    hdup[oh + j] = h; hdup[oh + H_ + j] = h; hdup[oh + 2 * H_ + j] = l;
    size_t ow = (size_t)b * KP_GATE + E_;
    wact[ow + j] = h; wact[ow + KCAT + j] = h; wact[ow + 2 * KCAT + j] = l;
}

__global__ void rsplit(const float* __restrict__ src, bf16* __restrict__ dst) {
    int idx = blockIdx.x * blockDim.x + threadIdx.x;
    if (idx >= B_ * F_) return;
    int b = idx >> 12, k = idx & (F_ - 1);
    bf16 h, l; split2(src[idx], h, l);
    size_t base = (size_t)b * KP_TS;
    dst[base + k] = h; dst[base + F_ + k] = l; dst[base + 2 * F_ + k] = h;
}

__global__ void reduce_rows(const float* __restrict__ sc, const float* __restrict__ lp,
                            float* __restrict__ lsum, float* __restrict__ tp,
                            float* __restrict__ dp) {
    int b = blockIdx.x, tid = threadIdx.x;
    float l = 0.f, t = 0.f, d0 = 0.f, d1 = 0.f, d2 = 0.f, d3 = 0.f;
    const float* tsr = sc + (size_t)b * B_;
    const float* dr0 = sc + (size_t)(1024 + b) * B_;
    const float* dr1 = sc + (size_t)(2048 + b) * B_;
    const float* dr2 = sc + (size_t)(3072 + b) * B_;
    const float* dr3 = sc + (size_t)(4096 + b) * B_;
    for (int k = tid; k < B_; k += 256) {
        float tv = tsr[k];
        float v0 = dr0[k], v1 = dr1[k], v2 = dr2[k], v3 = dr3[k];
        float h = fmaxf(0.f, 1.f - tv + v0) + fmaxf(0.f, 1.f - tv + v1)
                + fmaxf(0.f, 1.f - tv + v2) + fmaxf(0.f, 1.f - tv + v3);
        l += h * lp[k];
        t += expf(tv);
        d0 += expf(v0); d1 += expf(v1); d2 += expf(v2); d3 += expf(v3);
    }
    __shared__ float sh[6][256];
    sh[0][tid] = l; sh[1][tid] = t; sh[2][tid] = d0;
    sh[3][tid] = d1; sh[4][tid] = d2; sh[5][tid] = d3;
    __syncthreads();
    for (int s = 128; s > 0; s >>= 1) {
        if (tid < s)
            for (int q = 0; q < 6; q++) sh[q][tid] += sh[q][tid + s];
        __syncthreads();
    }
    if (tid == 0) {
        lsum[b] = sh[0][0]; tp[b] = sh[1][0];
        dp[b] = sh[2][0]; dp[B_ + b] = sh[3][0];
        dp[2 * B_ + b] = sh[4][0]; dp[3 * B_ + b] = sh[5][0];
    }
}

__global__ void finalize(const float* __restrict__ lsum, const float* __restrict__ tp,
                         const float* __restrict__ dp, float* __restrict__ out) {
    int tid = threadIdx.x;
    float lo = 0.f, an = 0.f;
    for (int b = tid; b < B_; b += 256) {
        lo += lsum[b];
        float t = tp[b];
        bool ok = (t >= dp[b]) && (t >= dp[B_ + b]) &&
                  (t >= dp[2 * B_ + b]) && (t >= dp[3 * B_ + b]);
        an += ok ? 1.0f : 0.0f;
    }
    __shared__ float s0[256], s1[256];
    s0[tid] = lo; s1[tid] = an;
    __syncthreads();
    for (int s = 128; s > 0; s >>= 1) {
        if (tid < s) { s0[tid] += s0[tid + s]; s1[tid] += s1[tid + s]; }
        __syncthreads();
    }
    if (tid == 0) {
        out[0] = -s0[0] / ((float)B_ * (float)B_);
        out[1] = s1[0] / (float)B_;
    }
}

// ---------------- host ----------------
#define SYM(p, g) cudaGetSymbolAddress((void**)&p, g)
static inline size_t gb1(size_t n) { return (n + 255) / 256; }
static inline size_t gb2(size_t n) { return (n / 2 + 255) / 256; }
#define GXN nullptr, nullptr, nullptr, nullptr, 0, 0, 0

extern "C" void kernel_launch(void* const* d_in, const int* in_sizes, int n_in,
                              void* d_out, int out_size) {
    (void)in_sizes; (void)n_in; (void)out_size;
    const float* target      = (const float*)d_in[0];
    const float* distractors = (const float*)d_in[1];
    const int*   start_tok   = (const int*)d_in[2];
    const float* emb_s   = (const float*)d_in[4];
    const float* Wih_s   = (const float*)d_in[5];
    const float* Whh_s   = (const float*)d_in[6];
    const float* bih_s   = (const float*)d_in[7];
    const float* bhh_s   = (const float*)d_in[8];
    const float* aff_s_W = (const float*)d_in[9];
    const float* aff_s_b = (const float*)d_in[10];
    const float* probs_W = (const float*)d_in[11];
    const float* probs_b = (const float*)d_in[12];
    const float* emb_r   = (const float*)d_in[13];
    const float* Wih_r   = (const float*)d_in[14];
    const float* Whh_r   = (const float*)d_in[15];
    const float* bih_r   = (const float*)d_in[16];
    const float* bhh_r   = (const float*)d_in[17];
    const float* aff_r_W = (const float*)d_in[18];
    const float* aff_r_b = (const float*)d_in[19];
    float* out = (float*)d_out;

    bf16 *pProbs, *pWcS, *pWcR, *pAfS, *pAfR, *pA5, *pRd, *pWa, *pWa2, *pHd, *pHd2;
    float *pHf, *pC, *pC2, *pG, *pG2, *pRf, *pSc, *pLp;
    float *pBs, *pBr, *pPb, *pLs, *pTp, *pDp, *pPm, *pPs;
    int *pMsg, *pPi;
    SYM(pProbs, d_probs); SYM(pWcS, d_wcat_s); SYM(pWcR, d_wcat_r);
    SYM(pAfS, d_affs); SYM(pAfR, d_affr); SYM(pA5, d_a5); SYM(pRd, d_rdup);
    SYM(pWa, d_wact); SYM(pWa2, d_wact2); SYM(pHd, d_hdup); SYM(pHd2, d_hdup2);
    SYM(pHf, g_hf); SYM(pC, g_c); SYM(pC2, g_c2); SYM(pG, g_gates); SYM(pG2, g_gates2);
    SYM(pRf, g_rf); SYM(pSc, g_sc); SYM(pLp, g_logprob);
    SYM(pBs, g_bias_s); SYM(pBr, g_bias_r); SYM(pPb, g_pbias);
    SYM(pLs, g_lsum); SYM(pTp, g_tp); SYM(pDp, g_dp); SYM(pMsg, g_msg);
    SYM(pPm, g_pmax); SYM(pPi, g_pidx); SYM(pPs, g_psum);

    cudaFuncSetAttribute(gemm_bf16<0>, cudaFuncAttributeMaxDynamicSharedMemorySize, SMEM_G);
    cudaFuncSetAttribute(gemm_bf16<1>, cudaFuncAttributeMaxDynamicSharedMemorySize, SMEM_G);
    cudaFuncSetAttribute(gemm_bf16<2>, cudaFuncAttributeMaxDynamicSharedMemorySize, SMEM_G);

    // ---- prep ----
    add_vec_perm<<<(G4H + 255) / 256, 256>>>(bih_s, bhh_s, pBs);
    add_vec_perm<<<(G4H + 255) / 256, 256>>>(bih_r, bhh_r, pBr);
    pad_bias<<<(NPAD + 255) / 256, 256>>>(probs_b, pPb);
    split_dupA2<<<gb2((size_t)B_ * F_), 256>>>(target, pA5, F_, (size_t)B_ * F_);
    split_dupA2<<<gb2((size_t)D_ * B_ * F_), 256>>>(distractors, pA5 + (size_t)B_ * KP_TS,
                                                    F_, (size_t)D_ * B_ * F_);
    split_dupB2<<<gb2((size_t)H_ * F_), 256>>>(aff_s_W, pAfS, F_, (size_t)H_ * F_);
    split_dupB2<<<gb2((size_t)F_ * H_), 256>>>(aff_r_W, pAfR, H_, (size_t)F_ * H_);
    split_dupB_pad2<<<gb2((size_t)NPAD * H_), 256>>>(probs_W, pProbs, V_, NPAD, H_);
    split_cat_perm2<<<gb2((size_t)G4H * KCAT), 256>>>(Wih_s, Whh_s, pWcS, E_, H_);
    split_cat_perm2<<<gb2((size_t)G4H * KCAT), 256>>>(Wih_r, Whh_r, pWcR, E_, H_);

    // ---- init ----
    zero_f<<<gb1((size_t)B_ * H_), 256>>>(pC, (size_t)B_ * H_);
    zero_f<<<gb1((size_t)B_ * H_), 256>>>(pC2, (size_t)B_ * H_);
    zero_w<<<gb1((size_t)B_ * KP_GATE / 2), 256>>>((uint32_t*)pWa2, (size_t)B_ * KP_GATE / 2);
    gemm_bf16<0><<<dim3(8, 8, 1), 256, SMEM_G>>>(pA5, pAfS, aff_s_b, pHf, KP_TS, H_, 0,
                                                 nullptr, nullptr, nullptr, GXN);
    hsplit_wact<<<gb1((size_t)B_ * H_), 256>>>(pHf, pHd, pWa);
    gather_split<<<B_, 128>>>(emb_s, start_tok, 1, pWa);

    // ---- main loop ----
    // sender gates(s) -> sender lstm(s) -> [logits(s) + recv gates(s-1)] ->
    // [argmax_gather(s) + recv lstm(s-1)]
    for (int s = 0; s < L_; s++) {
        gemm_bf16<0><<<dim3(8, 32, 1), 256, SMEM_G>>>(pWa, pWcS, pBs, pG, KP_GATE, G4H, 0,
                                                      nullptr, nullptr, nullptr, GXN);
        lstm_split_packed<<<gb1((size_t)B_ * H_), 256>>>(pG, pC, pHd, pWa);
        int zext = (s >= 1) ? 2 : 1;
        if (s < L_ - 1) {
            gemm_bf16<1><<<dim3(8, 157, zext), 256, SMEM_G>>>(
                pHd, pProbs, pPb, nullptr, KP_LOG, NPAD, 0, pPm, pPi, nullptr,
                pWa2, pWcR, pBr, pG2, KP_GATE, G4H, 32);
            argmax_gather<<<B_, 256>>>(pPm, pPi, 157, pMsg + s * B_,
                                       emb_s, pWa, emb_r, pWa2,
                                       pG2, pC2, pHd2, (s >= 1) ? 1 : 0);
        } else {
            gemm_bf16<2><<<dim3(8, 157, zext), 256, SMEM_G>>>(
                pHd, pProbs, pPb, nullptr, KP_LOG, NPAD, 0, pPm, pPi, pPs,
                pWa2, pWcR, pBr, pG2, KP_GATE, G4H, 32);
            lse_combine<<<B_, 32>>>(pPm, pPi, pPs, 157, pMsg + s * B_, pLp);
            // recv lstm(s-1): gates2 from the launch above
            lstm_split_packed<<<gb1((size_t)B_ * H_), 256>>>(pG2, pC2, pHd2, pWa2);
        }
    }

    // ---- receiver final step (r = L-1) ----
    gather_split<<<B_, 128>>>(emb_r, pMsg + (L_ - 1) * B_, 0, pWa2);
    gemm_bf16<0><<<dim3(8, 32, 1), 256, SMEM_G>>>(pWa2, pWcR, pBr, pG2, KP_GATE, G4H, 0,
                                                  nullptr, nullptr, nullptr, GXN);
    lstm_split_packed<<<gb1((size_t)B_ * H_), 256>>>(pG2, pC2, pHd2, pWa2);

    // ---- r, ts/ds, loss ----
    gemm_bf16<0><<<dim3(8, 32, 1), 256, SMEM_G>>>(pHd2, pAfR, aff_r_b, pRf, KP_LOG, F_, 0,
                                                  nullptr, nullptr, nullptr, GXN);
    rsplit<<<gb1((size_t)B_ * F_), 256>>>(pRf, pRd);
    gemm_bf16<0><<<dim3(8, 40, 1), 256, SMEM_G>>>(pA5, pRd, nullptr, pSc, KP_TS, B_, 1,
                                                  nullptr, nullptr, nullptr, GXN);
    reduce_rows<<<B_, 256>>>(pSc, pLp, pLs, pTp, pDp);
    finalize<<<1, 256>>>(pLs, pTp, pDp, out);
}